// round 1
// baseline (speedup 1.0000x reference)
#include <cuda_runtime.h>
#include <math.h>

// ---------------------------------------------------------------------------
// Problem constants (fixed by the reference)
// ---------------------------------------------------------------------------
#define NNODES 10000
#define NIN    2000
#define D1     500
#define D2     500
#define D3     2000
#define NZC    64
#define COMS_D 3064    // 500+500+2000+64

// ---------------------------------------------------------------------------
// Scratch (device globals; no allocations allowed)
// ---------------------------------------------------------------------------
__device__ float g_h1[NNODES * D1];
__device__ float g_h2[NNODES * D2];
__device__ float g_h3[NNODES * D3];
__device__ float g_z [NNODES * NZC];
__device__ float g_d1[NNODES * 2000];
__device__ float g_d2[NNODES * 500];
__device__ float g_d3[NNODES * 500];
__device__ float g_g [NNODES * 2000];     // gemm-before-spmm scratch (max dim 2000)
__device__ float g_t1[NNODES * 500];
__device__ float g_t2[NNODES * 500];
__device__ float g_t3[NNODES * 2000];
__device__ float g_t4[NNODES * NZC];
__device__ float g_u [NNODES * 5];
__device__ float g_zin[NNODES * COMS_D];
__device__ float g_zt [NNODES * NZC];     // z_in @ agcn_w (pre-spmm)
__device__ float g_ztopo[NNODES * NZC];
__device__ float g_scores[NNODES * 2];
__device__ float g_embp[NNODES * NZC];
__device__ float g_mean[4096];
__device__ float g_rstd[4096];

// ---------------------------------------------------------------------------
// SGEMM: C[M,Nc] = A[M,K] @ B[K,Nc] (+bias) (+elu)
// BM=BN=64, BK=16, 256 threads, 4x4 per thread
// mode: 0 = none, 1 = +bias, 2 = +bias then elu
// ---------------------------------------------------------------------------
#define BM 64
#define BN 64
#define BK 16

__global__ __launch_bounds__(256) void sgemm_kernel(
    const float* __restrict__ A, const float* __restrict__ B,
    const float* __restrict__ bias, float* __restrict__ C,
    int M, int Ncol, int K, int mode)
{
    __shared__ float As[BK][BM];
    __shared__ float Bs[BK][BN];

    int tid = threadIdx.x;
    int tx = tid & 15;          // 0..15
    int ty = tid >> 4;          // 0..15
    int bm = blockIdx.y * BM;
    int bn = blockIdx.x * BN;

    float acc[4][4];
#pragma unroll
    for (int i = 0; i < 4; i++)
#pragma unroll
        for (int j = 0; j < 4; j++) acc[i][j] = 0.f;

    int arow = tid >> 2;          // 0..63
    int acol = (tid & 3) * 4;     // 0,4,8,12
    int brow = tid >> 4;          // 0..15
    int bcol = (tid & 15) * 4;    // 0..60

    for (int k0 = 0; k0 < K; k0 += BK) {
        int gr = bm + arow;
#pragma unroll
        for (int i = 0; i < 4; i++) {
            int gk = k0 + acol + i;
            As[acol + i][arow] = (gr < M && gk < K) ? A[(size_t)gr * K + gk] : 0.f;
        }
        int gk = k0 + brow;
#pragma unroll
        for (int i = 0; i < 4; i++) {
            int gc = bn + bcol + i;
            Bs[brow][bcol + i] = (gk < K && gc < Ncol) ? B[(size_t)gk * Ncol + gc] : 0.f;
        }
        __syncthreads();

#pragma unroll
        for (int k = 0; k < BK; k++) {
            float4 a4 = *reinterpret_cast<const float4*>(&As[k][4 * ty]);
            float4 b4 = *reinterpret_cast<const float4*>(&Bs[k][4 * tx]);
            float ra[4] = {a4.x, a4.y, a4.z, a4.w};
            float rb[4] = {b4.x, b4.y, b4.z, b4.w};
#pragma unroll
            for (int i = 0; i < 4; i++)
#pragma unroll
                for (int j = 0; j < 4; j++)
                    acc[i][j] = fmaf(ra[i], rb[j], acc[i][j]);
        }
        __syncthreads();
    }

#pragma unroll
    for (int i = 0; i < 4; i++) {
        int row = bm + 4 * ty + i;
        if (row >= M) continue;
#pragma unroll
        for (int j = 0; j < 4; j++) {
            int col = bn + 4 * tx + j;
            if (col >= Ncol) continue;
            float v = acc[i][j];
            if (mode >= 1) v += bias[col];
            if (mode == 2) v = v > 0.f ? v : expm1f(v);
            C[(size_t)row * Ncol + col] = v;
        }
    }
}

static inline void gemm(const float* A, const float* B, const float* bias, float* C,
                        int M, int Ncol, int K, int mode)
{
    dim3 grid((Ncol + BN - 1) / BN, (M + BM - 1) / BM);
    sgemm_kernel<<<grid, 256>>>(A, B, bias, C, M, Ncol, K, mode);
}

// ---------------------------------------------------------------------------
// SpMM (COO, atomic): out[row[e], :] += val[e] * h[col[e], :]
// One thread per (edge, float4 of feature dim). D % 4 == 0.
// ---------------------------------------------------------------------------
__global__ void spmm_kernel(const float* __restrict__ h, const float* __restrict__ val,
                            const int* __restrict__ row, const int* __restrict__ col,
                            float* __restrict__ out, int D4, int E)
{
    long idx = (long)blockIdx.x * blockDim.x + threadIdx.x;
    long total = (long)E * D4;
    if (idx >= total) return;
    int e = (int)(idx / D4);
    int f = (int)(idx % D4);
    int r = row[e];
    int c = col[e];
    float v = val[e];
    float4 hv = reinterpret_cast<const float4*>(h)[(long)c * D4 + f];
    float* o = out + ((long)r * D4 + f) * 4;
    atomicAdd(o + 0, v * hv.x);
    atomicAdd(o + 1, v * hv.y);
    atomicAdd(o + 2, v * hv.z);
    atomicAdd(o + 3, v * hv.w);
}

static inline void spmm(const float* h, const float* val, const int* row, const int* col,
                        float* out, int D, int E)
{
    long total = (long)E * (D / 4);
    int blocks = (int)((total + 255) / 256);
    spmm_kernel<<<blocks, 256>>>(h, val, row, col, out, D / 4, E);
}

// ---------------------------------------------------------------------------
// Elementwise activation (in place). mode 0: elu(leaky_relu(x,0.2)); mode 1: elu(x)
// ---------------------------------------------------------------------------
__global__ void act_kernel(float* __restrict__ h, long n, int mode)
{
    long i = (long)blockIdx.x * blockDim.x + threadIdx.x;
    if (i >= n) return;
    float v = h[i];
    if (mode == 0) {
        h[i] = v > 0.f ? v : expm1f(0.2f * v);
    } else {
        h[i] = v > 0.f ? v : expm1f(v);
    }
}

static inline void act(float* h, long n, int mode)
{
    act_kernel<<<(int)((n + 255) / 256), 256>>>(h, n, mode);
}

// ---------------------------------------------------------------------------
// BatchNorm (affine=False, batch stats, biased variance)
// ---------------------------------------------------------------------------
__global__ void bn_stats_kernel(const float* __restrict__ h, int n, int d,
                                float* __restrict__ mean, float* __restrict__ rstd)
{
    __shared__ float ssum[8][32];
    __shared__ float ssq[8][32];
    int c = blockIdx.x * 32 + threadIdx.x;
    float s = 0.f, q = 0.f;
    if (c < d) {
        for (int r = threadIdx.y; r < n; r += 8) {
            float v = h[(size_t)r * d + c];
            s += v;
            q += v * v;
        }
    }
    ssum[threadIdx.y][threadIdx.x] = s;
    ssq[threadIdx.y][threadIdx.x] = q;
    __syncthreads();
    if (threadIdx.y == 0 && c < d) {
#pragma unroll
        for (int i = 1; i < 8; i++) {
            s += ssum[i][threadIdx.x];
            q += ssq[i][threadIdx.x];
        }
        float m = s / (float)n;
        float var = q / (float)n - m * m;
        if (var < 0.f) var = 0.f;
        mean[c] = m;
        rstd[c] = rsqrtf(var + 1e-5f);
    }
}

__global__ void bn_apply_kernel(const float* __restrict__ src, float* __restrict__ dst,
                                long total, int d,
                                const float* __restrict__ mean, const float* __restrict__ rstd)
{
    long i = (long)blockIdx.x * blockDim.x + threadIdx.x;
    if (i >= total) return;
    int c = (int)(i % d);
    dst[i] = (src[i] - mean[c]) * rstd[c];
}

static inline void batchnorm(const float* src, float* dst, int n, int d, float* mean, float* rstd)
{
    dim3 bt(32, 8);
    bn_stats_kernel<<<(d + 31) / 32, bt>>>(src, n, d, mean, rstd);
    long total = (long)n * d;
    bn_apply_kernel<<<(int)((total + 255) / 256), 256>>>(src, dst, total, d, mean, rstd);
}

// ---------------------------------------------------------------------------
// u = F.normalize(softmax(tanh(coms @ mlpl_w + mlpl_b), axis=1))  [N, 5]
// One warp per row; coms read piecewise from t1..t4.
// ---------------------------------------------------------------------------
__device__ __forceinline__ float coms_at(const float* t1, const float* t2,
                                         const float* t3, const float* t4,
                                         int n, int k)
{
    if (k < 500)  return t1[(size_t)n * 500 + k];
    if (k < 1000) return t2[(size_t)n * 500 + (k - 500)];
    if (k < 3000) return t3[(size_t)n * 2000 + (k - 1000)];
    return t4[(size_t)n * 64 + (k - 3000)];
}

__global__ void u_kernel(const float* __restrict__ t1, const float* __restrict__ t2,
                         const float* __restrict__ t3, const float* __restrict__ t4,
                         const float* __restrict__ W, const float* __restrict__ b,
                         float* __restrict__ u)
{
    int warp = (blockIdx.x * blockDim.x + threadIdx.x) >> 5;
    int lane = threadIdx.x & 31;
    if (warp >= NNODES) return;
    float acc[5] = {0.f, 0.f, 0.f, 0.f, 0.f};
    for (int k = lane; k < COMS_D; k += 32) {
        float v = coms_at(t1, t2, t3, t4, warp, k);
        const float* w = &W[(size_t)k * 5];
#pragma unroll
        for (int j = 0; j < 5; j++) acc[j] = fmaf(v, w[j], acc[j]);
    }
#pragma unroll
    for (int j = 0; j < 5; j++) {
        for (int off = 16; off > 0; off >>= 1)
            acc[j] += __shfl_down_sync(0xFFFFFFFF, acc[j], off);
    }
    if (lane == 0) {
        float l[5], m = -1e30f;
#pragma unroll
        for (int j = 0; j < 5; j++) { l[j] = tanhf(acc[j] + b[j]); m = fmaxf(m, l[j]); }
        float s = 0.f;
#pragma unroll
        for (int j = 0; j < 5; j++) { l[j] = expf(l[j] - m); s += l[j]; }
        float nrm = 0.f;
#pragma unroll
        for (int j = 0; j < 5; j++) { l[j] /= s; nrm += l[j] * l[j]; }
        nrm = fmaxf(sqrtf(nrm), 1e-12f);
#pragma unroll
        for (int j = 0; j < 5; j++) u[(size_t)warp * 5 + j] = l[j] / nrm;
    }
}

// ---------------------------------------------------------------------------
// z_in[n, k] = u[n, seg(k)] * coms[n, k]
// ---------------------------------------------------------------------------
__global__ void zin_kernel(const float* __restrict__ t1, const float* __restrict__ t2,
                           const float* __restrict__ t3, const float* __restrict__ t4,
                           const float* __restrict__ u, float* __restrict__ zin)
{
    long i = (long)blockIdx.x * blockDim.x + threadIdx.x;
    long total = (long)NNODES * COMS_D;
    if (i >= total) return;
    int n = (int)(i / COMS_D);
    int k = (int)(i % COMS_D);
    int seg = (k < 500) ? 0 : (k < 1000) ? 1 : (k < 3000) ? 2 : 3;
    zin[i] = u[(size_t)n * 5 + seg] * coms_at(t1, t2, t3, t4, n, k);
}

// ---------------------------------------------------------------------------
// Attention scores: score[n, br] = tanh(s @ W1 + b1) @ w2   (s = z or z_topo)
// One warp per (n, branch).
// ---------------------------------------------------------------------------
__global__ void att_scores_kernel(const float* __restrict__ z, const float* __restrict__ ztopo,
                                  const float* __restrict__ W1, const float* __restrict__ b1,
                                  const float* __restrict__ w2, float* __restrict__ scores)
{
    int gw = (blockIdx.x * blockDim.x + threadIdx.x) >> 5;
    int lane = threadIdx.x & 31;
    if (gw >= NNODES * 2) return;
    int n = gw >> 1;
    int br = gw & 1;
    const float* s = br ? &ztopo[(size_t)n * NZC] : &z[(size_t)n * NZC];
    float partial = 0.f;
    for (int j = lane; j < 128; j += 32) {
        float h = b1[j];
        for (int k = 0; k < NZC; k++) h = fmaf(s[k], W1[(size_t)k * 128 + j], h);
        partial = fmaf(tanhf(h), w2[j], partial);
    }
    for (int off = 16; off > 0; off >>= 1)
        partial += __shfl_down_sync(0xFFFFFFFF, partial, off);
    if (lane == 0) scores[(size_t)n * 2 + br] = partial;
}

__global__ void att_combine_kernel(const float* __restrict__ z, const float* __restrict__ ztopo,
                                   const float* __restrict__ scores, float* __restrict__ embp)
{
    long i = (long)blockIdx.x * blockDim.x + threadIdx.x;
    long total = (long)NNODES * NZC;
    if (i >= total) return;
    int n = (int)(i >> 6);
    float s0 = scores[(size_t)n * 2 + 0];
    float s1 = scores[(size_t)n * 2 + 1];
    float m = fmaxf(s0, s1);
    float e0 = expf(s0 - m), e1 = expf(s1 - m);
    float inv = 1.f / (e0 + e1);
    embp[i] = (e0 * inv) * z[i] + (e1 * inv) * ztopo[i];
}

// ---------------------------------------------------------------------------
// Row softmax over 64 columns (pred)
// ---------------------------------------------------------------------------
__global__ void rowsoftmax64_kernel(const float* __restrict__ in, float* __restrict__ out)
{
    int n = blockIdx.x;
    int t = threadIdx.x;
    __shared__ float sh[64];
    float v = in[(size_t)n * 64 + t];
    sh[t] = v;
    __syncthreads();
    for (int s = 32; s > 0; s >>= 1) {
        if (t < s) sh[t] = fmaxf(sh[t], sh[t + s]);
        __syncthreads();
    }
    float m = sh[0];
    __syncthreads();
    float e = expf(v - m);
    sh[t] = e;
    __syncthreads();
    for (int s = 32; s > 0; s >>= 1) {
        if (t < s) sh[t] += sh[t + s];
        __syncthreads();
    }
    out[(size_t)n * 64 + t] = e / sh[0];
}

// ---------------------------------------------------------------------------
// Student-t q: q[n,j] = (1 + ||z_n - c_j||^2)^-1, row-normalized (V=1)
// ---------------------------------------------------------------------------
__global__ void q_kernel(const float* __restrict__ z, const float* __restrict__ cluster,
                         float* __restrict__ q)
{
    int n = blockIdx.x;
    int t = threadIdx.x;   // 0..63 (cluster index)
    __shared__ float zs[64];
    __shared__ float red[64];
    zs[t] = z[(size_t)n * 64 + t];
    __syncthreads();
    float d2 = 0.f;
    const float* c = &cluster[(size_t)t * 64];
    for (int k = 0; k < 64; k++) {
        float diff = zs[k] - c[k];
        d2 = fmaf(diff, diff, d2);
    }
    float qv = 1.f / (1.f + d2);
    red[t] = qv;
    __syncthreads();
    for (int s = 32; s > 0; s >>= 1) {
        if (t < s) red[t] += red[t + s];
        __syncthreads();
    }
    q[(size_t)n * 64 + t] = qv / red[0];
}

// ---------------------------------------------------------------------------
// Launch
// ---------------------------------------------------------------------------
extern "C" void kernel_launch(void* const* d_in, const int* in_sizes, int n_in,
                              void* d_out, int out_size)
{
    const float* x       = (const float*)d_in[0];
    const float* adj_val = (const float*)d_in[1];
    const float* enc1_w  = (const float*)d_in[2];
    const float* enc1_b  = (const float*)d_in[3];
    const float* enc2_w  = (const float*)d_in[4];
    const float* enc2_b  = (const float*)d_in[5];
    const float* enc3_w  = (const float*)d_in[6];
    const float* enc3_b  = (const float*)d_in[7];
    const float* zl_w    = (const float*)d_in[8];
    const float* zl_b    = (const float*)d_in[9];
    const float* dec1_w  = (const float*)d_in[10];
    const float* dec1_b  = (const float*)d_in[11];
    const float* dec2_w  = (const float*)d_in[12];
    const float* dec2_b  = (const float*)d_in[13];
    const float* dec3_w  = (const float*)d_in[14];
    const float* dec3_b  = (const float*)d_in[15];
    const float* xbar_w  = (const float*)d_in[16];
    const float* xbar_b  = (const float*)d_in[17];
    const float* t1_w    = (const float*)d_in[18];
    const float* t2_w    = (const float*)d_in[19];
    const float* t3_w    = (const float*)d_in[20];
    const float* t4_w    = (const float*)d_in[21];
    const float* agcn_w  = (const float*)d_in[22];
    const float* mlpl_w  = (const float*)d_in[23];
    const float* mlpl_b  = (const float*)d_in[24];
    const float* att_w1  = (const float*)d_in[25];
    const float* att_b1  = (const float*)d_in[26];
    const float* att_w2  = (const float*)d_in[27];
    const float* cluster = (const float*)d_in[28];
    const int*   adj_row = (const int*)d_in[29];
    const int*   adj_col = (const int*)d_in[30];
    const int E = in_sizes[1];

    float* out      = (float*)d_out;
    float* out_xbar = out;
    float* out_q    = out + (size_t)NNODES * NIN;
    float* out_pred = out_q + (size_t)NNODES * NZC;
    float* out_emb  = out_pred + (size_t)NNODES * NZC;

    float *h1, *h2, *h3, *z, *d1, *d2, *d3, *g, *t1, *t2, *t3, *t4;
    float *u, *zin, *zt, *ztopo, *scores, *embp, *mean, *rstd;
    cudaGetSymbolAddress((void**)&h1, g_h1);
    cudaGetSymbolAddress((void**)&h2, g_h2);
    cudaGetSymbolAddress((void**)&h3, g_h3);
    cudaGetSymbolAddress((void**)&z,  g_z);
    cudaGetSymbolAddress((void**)&d1, g_d1);
    cudaGetSymbolAddress((void**)&d2, g_d2);
    cudaGetSymbolAddress((void**)&d3, g_d3);
    cudaGetSymbolAddress((void**)&g,  g_g);
    cudaGetSymbolAddress((void**)&t1, g_t1);
    cudaGetSymbolAddress((void**)&t2, g_t2);
    cudaGetSymbolAddress((void**)&t3, g_t3);
    cudaGetSymbolAddress((void**)&t4, g_t4);
    cudaGetSymbolAddress((void**)&u,  g_u);
    cudaGetSymbolAddress((void**)&zin, g_zin);
    cudaGetSymbolAddress((void**)&zt, g_zt);
    cudaGetSymbolAddress((void**)&ztopo, g_ztopo);
    cudaGetSymbolAddress((void**)&scores, g_scores);
    cudaGetSymbolAddress((void**)&embp, g_embp);
    cudaGetSymbolAddress((void**)&mean, g_mean);
    cudaGetSymbolAddress((void**)&rstd, g_rstd);

    // ---------------- AE ----------------
    gemm(x,  enc1_w, enc1_b, h1, NNODES, D1,   NIN, 2);
    gemm(h1, enc2_w, enc2_b, h2, NNODES, D2,   D1,  2);
    gemm(h2, enc3_w, enc3_b, h3, NNODES, D3,   D2,  2);
    gemm(h3, zl_w,   zl_b,   z,  NNODES, NZC,  D3,  1);
    gemm(z,  dec1_w, dec1_b, d1, NNODES, 2000, NZC, 2);
    gemm(d1, dec2_w, dec2_b, d2, NNODES, 500,  2000, 2);
    gemm(d2, dec3_w, dec3_b, d3, NNODES, 500,  500, 2);
    gemm(d3, xbar_w, xbar_b, out_xbar, NNODES, NIN, 500, 1);

    // ---------------- topo GCN stack ----------------
    // t1
    gemm(x, t1_w, nullptr, g, NNODES, 500, NIN, 0);
    cudaMemsetAsync(t1, 0, (size_t)NNODES * 500 * sizeof(float), 0);
    spmm(g, adj_val, adj_row, adj_col, t1, 500, E);
    act(t1, (long)NNODES * 500, 0);
    batchnorm(t1, t1, NNODES, 500, mean, rstd);
    // t2
    gemm(t1, t2_w, nullptr, g, NNODES, 500, 500, 0);
    cudaMemsetAsync(t2, 0, (size_t)NNODES * 500 * sizeof(float), 0);
    spmm(g, adj_val, adj_row, adj_col, t2, 500, E);
    act(t2, (long)NNODES * 500, 0);
    batchnorm(t2, t2, NNODES, 500, mean, rstd);
    // t3
    gemm(t2, t3_w, nullptr, g, NNODES, 2000, 500, 0);
    cudaMemsetAsync(t3, 0, (size_t)NNODES * 2000 * sizeof(float), 0);
    spmm(g, adj_val, adj_row, adj_col, t3, 2000, E);
    act(t3, (long)NNODES * 2000, 0);
    batchnorm(t3, t3, NNODES, 2000, mean, rstd);
    // t4
    gemm(t3, t4_w, nullptr, g, NNODES, NZC, 2000, 0);
    cudaMemsetAsync(t4, 0, (size_t)NNODES * NZC * sizeof(float), 0);
    spmm(g, adj_val, adj_row, adj_col, t4, NZC, E);
    act(t4, (long)NNODES * NZC, 0);
    batchnorm(t4, t4, NNODES, NZC, mean, rstd);

    // ---------------- MLP gate u + z_in + agcn ----------------
    u_kernel<<<(NNODES * 32 + 255) / 256, 256>>>(t1, t2, t3, t4, mlpl_w, mlpl_b, u);
    {
        long total = (long)NNODES * COMS_D;
        zin_kernel<<<(int)((total + 255) / 256), 256>>>(t1, t2, t3, t4, u, zin);
    }
    gemm(zin, agcn_w, nullptr, zt, NNODES, NZC, COMS_D, 0);
    cudaMemsetAsync(ztopo, 0, (size_t)NNODES * NZC * sizeof(float), 0);
    spmm(zt, adj_val, adj_row, adj_col, ztopo, NZC, E);
    act(ztopo, (long)NNODES * NZC, 1);   // elu only (active=False)
    batchnorm(ztopo, ztopo, NNODES, NZC, mean, rstd);

    // ---------------- attention fusion ----------------
    att_scores_kernel<<<(NNODES * 2 * 32 + 255) / 256, 256>>>(z, ztopo, att_w1, att_b1, att_w2, scores);
    {
        long total = (long)NNODES * NZC;
        att_combine_kernel<<<(int)((total + 255) / 256), 256>>>(z, ztopo, scores, embp);
    }
    batchnorm(embp, out_emb, NNODES, NZC, mean, rstd);
    rowsoftmax64_kernel<<<NNODES, 64>>>(out_emb, out_pred);

    // ---------------- Student-t q ----------------
    q_kernel<<<NNODES, 64>>>(z, cluster, out_q);
}

// round 5
// speedup vs baseline: 1.8548x; 1.8548x over previous
#include <cuda_runtime.h>
#include <cuda_bf16.h>
#include <math.h>
#include <stdint.h>

// ---------------------------------------------------------------------------
// Problem constants
// ---------------------------------------------------------------------------
#define NNODES 10000
#define NIN    2000
#define D1     500
#define D2     500
#define D3     2000
#define NZC    64
#define COMS_D 3064

// ---------------------------------------------------------------------------
// Scratch (device globals; no allocations allowed)
// ---------------------------------------------------------------------------
__device__ float g_h1[NNODES * D1];
__device__ float g_h2[NNODES * D2];
__device__ float g_h3[NNODES * D3];
__device__ float g_z [NNODES * NZC];
__device__ float g_d1[NNODES * 2000];
__device__ float g_d2[NNODES * 500];
__device__ float g_d3[NNODES * 500];
__device__ float g_g [NNODES * 2000];
__device__ float g_t1[NNODES * 500];
__device__ float g_t2[NNODES * 500];
__device__ float g_t3[NNODES * 2000];
__device__ float g_t4[NNODES * NZC];
__device__ float g_u [NNODES * 5];
__device__ float g_zin[NNODES * COMS_D];
__device__ float g_zt [NNODES * NZC];
__device__ float g_ztopo[NNODES * NZC];
__device__ float g_scores[NNODES * 2];
__device__ float g_embp[NNODES * NZC];
__device__ float g_mean[4096];
__device__ float g_rstd[4096];

// bf16 split-precision scratch (A: [M,Kpad] K-major; W: [N,Kpad] K-major)
__device__ __align__(256) __nv_bfloat16 g_Ahi[(size_t)NNODES * 3072];
__device__ __align__(256) __nv_bfloat16 g_Alo[(size_t)NNODES * 3072];
__device__ __align__(256) __nv_bfloat16 g_Whi[2048 * 3072];
__device__ __align__(256) __nv_bfloat16 g_Wlo[2048 * 3072];

// ---------------------------------------------------------------------------
// PTX helpers (ldmatrix / mma.sync only — no cp.async anywhere)
// ---------------------------------------------------------------------------
__device__ __forceinline__ void ldsm4(uint32_t* r, uint32_t addr) {
    asm volatile("ldmatrix.sync.aligned.m8n8.x4.shared.b16 {%0,%1,%2,%3}, [%4];"
                 : "=r"(r[0]), "=r"(r[1]), "=r"(r[2]), "=r"(r[3]) : "r"(addr));
}
__device__ __forceinline__ uint32_t smem_u32(const void* p) {
    uint32_t a;
    asm("{ .reg .u64 t; cvta.to.shared.u64 t, %1; cvt.u32.u64 %0, t; }" : "=r"(a) : "l"(p));
    return a;
}
__device__ __forceinline__ void mma16816(float* c, const uint32_t* a, const uint32_t* b) {
    asm volatile(
        "mma.sync.aligned.m16n8k16.row.col.f32.bf16.bf16.f32 "
        "{%0,%1,%2,%3}, {%4,%5,%6,%7}, {%8,%9}, {%0,%1,%2,%3};"
        : "+f"(c[0]), "+f"(c[1]), "+f"(c[2]), "+f"(c[3])
        : "r"(a[0]), "r"(a[1]), "r"(a[2]), "r"(a[3]), "r"(b[0]), "r"(b[1]));
}

// ---------------------------------------------------------------------------
// Split-bf16 mma.sync GEMM: C[M,N] = A[M,K] @ B[K,N]
// A hi/lo [M,Kpad], W hi/lo [N,Kpad] (pre-transposed). BM=128 BN=64 BK=32.
// 256 threads, warps 4(m) x 2(n), warp tile 32x32.
// Register prefetch -> st.shared, single smem stage (30720B < 48KB default).
// Skewed smem rows: 80B per 32-element K row -> ldmatrix conflict-free.
// mode: 0 none, 1 +bias, 2 +bias+elu
// ---------------------------------------------------------------------------
#define ROWB 80                     // bytes per smem row (32 bf16 + 8 skew)
#define A_BYTES (128 * ROWB)        // 10240
#define B_BYTES (64 * ROWB)         // 5120
#define GEMM_SMEM (2 * A_BYTES + 2 * B_BYTES)   // 30720

struct Prefetch {
    uint4 ahi[2], alo[2], bhi, blo;
};

__device__ __forceinline__ void fetch_regs(
    Prefetch& p,
    const __nv_bfloat16* __restrict__ Ahi, const __nv_bfloat16* __restrict__ Alo,
    const __nv_bfloat16* __restrict__ Bhi, const __nv_bfloat16* __restrict__ Blo,
    int mBase, int M, int nBase, int N, int Kpad, int k0, int tid)
{
#pragma unroll
    for (int it = 0; it < 2; it++) {
        int t = tid + it * 256;
        int row = t >> 2, seg = t & 3;
        int gr = mBase + row;
        int sr = (gr < M) ? gr : 0;       // clamp: garbage rows masked in epilogue
        size_t off = (size_t)sr * Kpad + k0 + seg * 8;
        p.ahi[it] = *reinterpret_cast<const uint4*>(Ahi + off);
        p.alo[it] = *reinterpret_cast<const uint4*>(Alo + off);
    }
    {
        int row = tid >> 2, seg = tid & 3;
        int gn = nBase + row;
        int sn = (gn < N) ? gn : 0;
        size_t off = (size_t)sn * Kpad + k0 + seg * 8;
        p.bhi = *reinterpret_cast<const uint4*>(Bhi + off);
        p.blo = *reinterpret_cast<const uint4*>(Blo + off);
    }
}

__global__ __launch_bounds__(256) void mma_gemm_kernel(
    const __nv_bfloat16* __restrict__ Ahi, const __nv_bfloat16* __restrict__ Alo,
    const __nv_bfloat16* __restrict__ Bhi, const __nv_bfloat16* __restrict__ Blo,
    const float* __restrict__ bias, float* __restrict__ C,
    int M, int Ncol, int Kpad, int mode)
{
    __shared__ __align__(256) char smem[GEMM_SMEM];
    uint32_t sb = smem_u32(smem);
    int tid = threadIdx.x;
    int wid = tid >> 5, lane = tid & 31;
    int wm = wid & 3;          // m-warp 0..3
    int wn = wid >> 2;         // n-warp 0..1
    int mBase = blockIdx.y * 128;
    int nBase = blockIdx.x * 64;

    uint32_t aHiS = sb;
    uint32_t aLoS = sb + A_BYTES;
    uint32_t bHiS = sb + 2 * A_BYTES;
    uint32_t bLoS = bHiS + B_BYTES;

    // per-thread smem store offsets
    int arow0 = tid >> 2, aseg = tid & 3;
    uint32_t aOff0 = arow0 * ROWB + aseg * 16;
    uint32_t aOff1 = (arow0 + 64) * ROWB + aseg * 16;
    uint32_t bOff  = aOff0;   // B uses rows 0..63, same formula

    float acc[2][4][4];
#pragma unroll
    for (int mt = 0; mt < 2; mt++)
#pragma unroll
        for (int nt = 0; nt < 4; nt++)
#pragma unroll
            for (int r = 0; r < 4; r++) acc[mt][nt][r] = 0.f;

    const int nc = Kpad >> 5;   // BK=32 chunks

    Prefetch pf;
    fetch_regs(pf, Ahi, Alo, Bhi, Blo, mBase, M, nBase, Ncol, Kpad, 0, tid);

    // ldmatrix lane addressing
    int lrow = (lane & 7) + ((lane >> 3) & 1) * 8;
    int lcol8 = (lane >> 4) * 8;

    for (int c = 0; c < nc; c++) {
        // regs -> smem
        *reinterpret_cast<uint4*>(smem + aOff0)                        = pf.ahi[0];
        *reinterpret_cast<uint4*>(smem + aOff1)                        = pf.ahi[1];
        *reinterpret_cast<uint4*>(smem + A_BYTES + aOff0)              = pf.alo[0];
        *reinterpret_cast<uint4*>(smem + A_BYTES + aOff1)              = pf.alo[1];
        *reinterpret_cast<uint4*>(smem + 2 * A_BYTES + bOff)           = pf.bhi;
        *reinterpret_cast<uint4*>(smem + 2 * A_BYTES + B_BYTES + bOff) = pf.blo;
        __syncthreads();

        // issue next chunk's global loads (overlap with compute below)
        if (c + 1 < nc)
            fetch_regs(pf, Ahi, Alo, Bhi, Blo, mBase, M, nBase, Ncol, Kpad, (c + 1) * 32, tid);

#pragma unroll
        for (int ks = 0; ks < 2; ks++) {
            int kc = ks * 16 + lcol8;
            uint32_t ah[2][4], al[2][4];
#pragma unroll
            for (int mt = 0; mt < 2; mt++) {
                uint32_t o = (wm * 32 + mt * 16 + lrow) * ROWB + kc * 2;
                ldsm4(ah[mt], aHiS + o);
                ldsm4(al[mt], aLoS + o);
            }
            uint32_t bh[4][2], bl[4][2];
#pragma unroll
            for (int ntp = 0; ntp < 2; ntp++) {
                uint32_t o = (wn * 32 + ntp * 16 + lrow) * ROWB + kc * 2;
                uint32_t t[4];
                ldsm4(t, bHiS + o);
                bh[2 * ntp][0] = t[0]; bh[2 * ntp][1] = t[2];
                bh[2 * ntp + 1][0] = t[1]; bh[2 * ntp + 1][1] = t[3];
                ldsm4(t, bLoS + o);
                bl[2 * ntp][0] = t[0]; bl[2 * ntp][1] = t[2];
                bl[2 * ntp + 1][0] = t[1]; bl[2 * ntp + 1][1] = t[3];
            }
#pragma unroll
            for (int mt = 0; mt < 2; mt++)
#pragma unroll
                for (int nt = 0; nt < 4; nt++) {
                    mma16816(acc[mt][nt], ah[mt], bh[nt]);
                    mma16816(acc[mt][nt], ah[mt], bl[nt]);
                    mma16816(acc[mt][nt], al[mt], bh[nt]);
                }
        }
        __syncthreads();
    }

    // Epilogue: direct global stores (frag layout m16n8)
    int qr = lane >> 2;
    int qc = (lane & 3) * 2;
#pragma unroll
    for (int mt = 0; mt < 2; mt++) {
#pragma unroll
        for (int nt = 0; nt < 4; nt++) {
#pragma unroll
            for (int half = 0; half < 2; half++) {
                int gr = mBase + wm * 32 + mt * 16 + qr + half * 8;
                if (gr >= M) continue;
#pragma unroll
                for (int e = 0; e < 2; e++) {
                    int gc = nBase + wn * 32 + nt * 8 + qc + e;
                    if (gc >= Ncol) continue;
                    float v = acc[mt][nt][half * 2 + e];
                    if (mode >= 1) v += bias[gc];
                    if (mode == 2) v = v > 0.f ? v : expm1f(v);
                    C[(size_t)gr * Ncol + gc] = v;
                }
            }
        }
    }
}

// ---------------------------------------------------------------------------
// fp32 -> (hi,lo) bf16 conversions
// ---------------------------------------------------------------------------
__global__ void convA_kernel(const float* __restrict__ src,
                             __nv_bfloat16* __restrict__ hi, __nv_bfloat16* __restrict__ lo,
                             int K, int Kpad, long total)
{
    long i = (long)blockIdx.x * blockDim.x + threadIdx.x;
    if (i >= total) return;
    long r = i / Kpad;
    int  k = (int)(i - r * Kpad);
    float v = (k < K) ? src[r * K + k] : 0.f;
    __nv_bfloat16 h = __float2bfloat16(v);
    hi[i] = h;
    lo[i] = __float2bfloat16(v - __bfloat162float(h));
}

__global__ void convBT_kernel(const float* __restrict__ B,
                              __nv_bfloat16* __restrict__ bhi, __nv_bfloat16* __restrict__ blo,
                              int K, int N, int Kpad)
{
    __shared__ float sm[32][33];
    int k0 = blockIdx.x * 32, n0 = blockIdx.y * 32;
    int tx = threadIdx.x, ty = threadIdx.y;
    for (int i = ty; i < 32; i += 8) {
        int k = k0 + i, n = n0 + tx;
        sm[i][tx] = (k < K && n < N) ? B[(size_t)k * N + n] : 0.f;
    }
    __syncthreads();
    for (int i = ty; i < 32; i += 8) {
        int n = n0 + i, k = k0 + tx;
        if (n < N && k < Kpad) {
            float v = sm[tx][i];
            __nv_bfloat16 h = __float2bfloat16(v);
            bhi[(size_t)n * Kpad + k] = h;
            blo[(size_t)n * Kpad + k] = __float2bfloat16(v - __bfloat162float(h));
        }
    }
}

// ---------------------------------------------------------------------------
// SpMM (COO, atomic)
// ---------------------------------------------------------------------------
__global__ void spmm_kernel(const float* __restrict__ h, const float* __restrict__ val,
                            const int* __restrict__ row, const int* __restrict__ col,
                            float* __restrict__ out, int D4, int E)
{
    long idx = (long)blockIdx.x * blockDim.x + threadIdx.x;
    long total = (long)E * D4;
    if (idx >= total) return;
    int e = (int)(idx / D4);
    int f = (int)(idx % D4);
    int r = row[e];
    int c = col[e];
    float v = val[e];
    float4 hv = reinterpret_cast<const float4*>(h)[(long)c * D4 + f];
    float* o = out + ((long)r * D4 + f) * 4;
    atomicAdd(o + 0, v * hv.x);
    atomicAdd(o + 1, v * hv.y);
    atomicAdd(o + 2, v * hv.z);
    atomicAdd(o + 3, v * hv.w);
}
static inline void spmm(const float* h, const float* val, const int* row, const int* col,
                        float* out, int D, int E)
{
    long total = (long)E * (D / 4);
    spmm_kernel<<<(int)((total + 255) / 256), 256>>>(h, val, row, col, out, D / 4, E);
}

// ---------------------------------------------------------------------------
// Activations / BatchNorm
// ---------------------------------------------------------------------------
__global__ void act_kernel(float* __restrict__ h, long n, int mode)
{
    long i = (long)blockIdx.x * blockDim.x + threadIdx.x;
    if (i >= n) return;
    float v = h[i];
    h[i] = v > 0.f ? v : (mode == 0 ? expm1f(0.2f * v) : expm1f(v));
}
static inline void act(float* h, long n, int mode)
{
    act_kernel<<<(int)((n + 255) / 256), 256>>>(h, n, mode);
}

__global__ void bn_stats_kernel(const float* __restrict__ h, int n, int d,
                                float* __restrict__ mean, float* __restrict__ rstd)
{
    __shared__ float ssum[8][32];
    __shared__ float ssq[8][32];
    int c = blockIdx.x * 32 + threadIdx.x;
    float s = 0.f, q = 0.f;
    if (c < d) {
        for (int r = threadIdx.y; r < n; r += 8) {
            float v = h[(size_t)r * d + c];
            s += v; q += v * v;
        }
    }
    ssum[threadIdx.y][threadIdx.x] = s;
    ssq[threadIdx.y][threadIdx.x] = q;
    __syncthreads();
    if (threadIdx.y == 0 && c < d) {
#pragma unroll
        for (int i = 1; i < 8; i++) { s += ssum[i][threadIdx.x]; q += ssq[i][threadIdx.x]; }
        float m = s / (float)n;
        float var = q / (float)n - m * m;
        if (var < 0.f) var = 0.f;
        mean[c] = m;
        rstd[c] = rsqrtf(var + 1e-5f);
    }
}
__global__ void bn_apply_kernel(const float* __restrict__ src, float* __restrict__ dst,
                                long total, int d,
                                const float* __restrict__ mean, const float* __restrict__ rstd)
{
    long i = (long)blockIdx.x * blockDim.x + threadIdx.x;
    if (i >= total) return;
    int c = (int)(i % d);
    dst[i] = (src[i] - mean[c]) * rstd[c];
}
static inline void batchnorm(const float* src, float* dst, int n, int d, float* mean, float* rstd)
{
    dim3 bt(32, 8);
    bn_stats_kernel<<<(d + 31) / 32, bt>>>(src, n, d, mean, rstd);
    long total = (long)n * d;
    bn_apply_kernel<<<(int)((total + 255) / 256), 256>>>(src, dst, total, d, mean, rstd);
}

// ---------------------------------------------------------------------------
// Gate u, z_in, attention, softmax, q
// ---------------------------------------------------------------------------
__device__ __forceinline__ float coms_at(const float* t1, const float* t2,
                                         const float* t3, const float* t4,
                                         int n, int k)
{
    if (k < 500)  return t1[(size_t)n * 500 + k];
    if (k < 1000) return t2[(size_t)n * 500 + (k - 500)];
    if (k < 3000) return t3[(size_t)n * 2000 + (k - 1000)];
    return t4[(size_t)n * 64 + (k - 3000)];
}

__global__ void u_kernel(const float* __restrict__ t1, const float* __restrict__ t2,
                         const float* __restrict__ t3, const float* __restrict__ t4,
                         const float* __restrict__ W, const float* __restrict__ b,
                         float* __restrict__ u)
{
    int warp = (blockIdx.x * blockDim.x + threadIdx.x) >> 5;
    int lane = threadIdx.x & 31;
    if (warp >= NNODES) return;
    float acc[5] = {0.f, 0.f, 0.f, 0.f, 0.f};
    for (int k = lane; k < COMS_D; k += 32) {
        float v = coms_at(t1, t2, t3, t4, warp, k);
        const float* w = &W[(size_t)k * 5];
#pragma unroll
        for (int j = 0; j < 5; j++) acc[j] = fmaf(v, w[j], acc[j]);
    }
#pragma unroll
    for (int j = 0; j < 5; j++) {
        for (int off = 16; off > 0; off >>= 1)
            acc[j] += __shfl_down_sync(0xFFFFFFFF, acc[j], off);
    }
    if (lane == 0) {
        float l[5], m = -1e30f;
#pragma unroll
        for (int j = 0; j < 5; j++) { l[j] = tanhf(acc[j] + b[j]); m = fmaxf(m, l[j]); }
        float s = 0.f;
#pragma unroll
        for (int j = 0; j < 5; j++) { l[j] = expf(l[j] - m); s += l[j]; }
        float nrm = 0.f;
#pragma unroll
        for (int j = 0; j < 5; j++) { l[j] /= s; nrm += l[j] * l[j]; }
        nrm = fmaxf(sqrtf(nrm), 1e-12f);
#pragma unroll
        for (int j = 0; j < 5; j++) u[(size_t)warp * 5 + j] = l[j] / nrm;
    }
}

__global__ void zin_kernel(const float* __restrict__ t1, const float* __restrict__ t2,
                           const float* __restrict__ t3, const float* __restrict__ t4,
                           const float* __restrict__ u, float* __restrict__ zin)
{
    long i = (long)blockIdx.x * blockDim.x + threadIdx.x;
    long total = (long)NNODES * COMS_D;
    if (i >= total) return;
    int n = (int)(i / COMS_D);
    int k = (int)(i % COMS_D);
    int seg = (k < 500) ? 0 : (k < 1000) ? 1 : (k < 3000) ? 2 : 3;
    zin[i] = u[(size_t)n * 5 + seg] * coms_at(t1, t2, t3, t4, n, k);
}

__global__ void att_scores_kernel(const float* __restrict__ z, const float* __restrict__ ztopo,
                                  const float* __restrict__ W1, const float* __restrict__ b1,
                                  const float* __restrict__ w2, float* __restrict__ scores)
{
    int gw = (blockIdx.x * blockDim.x + threadIdx.x) >> 5;
    int lane = threadIdx.x & 31;
    if (gw >= NNODES * 2) return;
    int n = gw >> 1;
    int br = gw & 1;
    const float* s = br ? &ztopo[(size_t)n * NZC] : &z[(size_t)n * NZC];
    float partial = 0.f;
    for (int j = lane; j < 128; j += 32) {
        float h = b1[j];
        for (int k = 0; k < NZC; k++) h = fmaf(s[k], W1[(size_t)k * 128 + j], h);
        partial = fmaf(tanhf(h), w2[j], partial);
    }
    for (int off = 16; off > 0; off >>= 1)
        partial += __shfl_down_sync(0xFFFFFFFF, partial, off);
    if (lane == 0) scores[(size_t)n * 2 + br] = partial;
}

__global__ void att_combine_kernel(const float* __restrict__ z, const float* __restrict__ ztopo,
                                   const float* __restrict__ scores, float* __restrict__ embp)
{
    long i = (long)blockIdx.x * blockDim.x + threadIdx.x;
    long total = (long)NNODES * NZC;
    if (i >= total) return;
    int n = (int)(i >> 6);
    float s0 = scores[(size_t)n * 2 + 0];
    float s1 = scores[(size_t)n * 2 + 1];
    float m = fmaxf(s0, s1);
    float e0 = expf(s0 - m), e1 = expf(s1 - m);
    float inv = 1.f / (e0 + e1);
    embp[i] = (e0 * inv) * z[i] + (e1 * inv) * ztopo[i];
}

__global__ void rowsoftmax64_kernel(const float* __restrict__ in, float* __restrict__ out)
{
    int n = blockIdx.x;
    int t = threadIdx.x;
    __shared__ float sh[64];
    float v = in[(size_t)n * 64 + t];
    sh[t] = v;
    __syncthreads();
    for (int s = 32; s > 0; s >>= 1) {
        if (t < s) sh[t] = fmaxf(sh[t], sh[t + s]);
        __syncthreads();
    }
    float m = sh[0];
    __syncthreads();
    float e = expf(v - m);
    sh[t] = e;
    __syncthreads();
    for (int s = 32; s > 0; s >>= 1) {
        if (t < s) sh[t] += sh[t + s];
        __syncthreads();
    }
    out[(size_t)n * 64 + t] = e / sh[0];
}

__global__ void q_kernel(const float* __restrict__ z, const float* __restrict__ cluster,
                         float* __restrict__ q)
{
    int n = blockIdx.x;
    int t = threadIdx.x;
    __shared__ float zs[64];
    __shared__ float red[64];
    zs[t] = z[(size_t)n * 64 + t];
    __syncthreads();
    float d2 = 0.f;
    const float* c = &cluster[(size_t)t * 64];
    for (int k = 0; k < 64; k++) {
        float diff = zs[k] - c[k];
        d2 = fmaf(diff, diff, d2);
    }
    float qv = 1.f / (1.f + d2);
    red[t] = qv;
    __syncthreads();
    for (int s = 32; s > 0; s >>= 1) {
        if (t < s) red[t] += red[t + s];
        __syncthreads();
    }
    q[(size_t)n * 64 + t] = qv / red[0];
}

// ---------------------------------------------------------------------------
// Host-side GEMM dispatch
// ---------------------------------------------------------------------------
static inline void gemm_tc(const float* A, const float* Bw, const float* bias, float* C,
                           int M, int N, int K, int mode,
                           __nv_bfloat16* Ahi, __nv_bfloat16* Alo,
                           __nv_bfloat16* Whi, __nv_bfloat16* Wlo)
{
    int Kpad = (K + 31) & ~31;
    long tA = (long)M * Kpad;
    convA_kernel<<<(int)((tA + 255) / 256), 256>>>(A, Ahi, Alo, K, Kpad, tA);
    dim3 tg((Kpad + 31) / 32, (N + 31) / 32);
    convBT_kernel<<<tg, dim3(32, 8)>>>(Bw, Whi, Wlo, K, N, Kpad);

    dim3 grid((N + 63) / 64, (M + 127) / 128);
    mma_gemm_kernel<<<grid, 256>>>(Ahi, Alo, Whi, Wlo, bias, C, M, N, Kpad, mode);
}

// ---------------------------------------------------------------------------
// Launch
// ---------------------------------------------------------------------------
extern "C" void kernel_launch(void* const* d_in, const int* in_sizes, int n_in,
                              void* d_out, int out_size)
{
    const float* x       = (const float*)d_in[0];
    const float* adj_val = (const float*)d_in[1];
    const float* enc1_w  = (const float*)d_in[2];
    const float* enc1_b  = (const float*)d_in[3];
    const float* enc2_w  = (const float*)d_in[4];
    const float* enc2_b  = (const float*)d_in[5];
    const float* enc3_w  = (const float*)d_in[6];
    const float* enc3_b  = (const float*)d_in[7];
    const float* zl_w    = (const float*)d_in[8];
    const float* zl_b    = (const float*)d_in[9];
    const float* dec1_w  = (const float*)d_in[10];
    const float* dec1_b  = (const float*)d_in[11];
    const float* dec2_w  = (const float*)d_in[12];
    const float* dec2_b  = (const float*)d_in[13];
    const float* dec3_w  = (const float*)d_in[14];
    const float* dec3_b  = (const float*)d_in[15];
    const float* xbar_w  = (const float*)d_in[16];
    const float* xbar_b  = (const float*)d_in[17];
    const float* t1_w    = (const float*)d_in[18];
    const float* t2_w    = (const float*)d_in[19];
    const float* t3_w    = (const float*)d_in[20];
    const float* t4_w    = (const float*)d_in[21];
    const float* agcn_w  = (const float*)d_in[22];
    const float* mlpl_w  = (const float*)d_in[23];
    const float* mlpl_b  = (const float*)d_in[24];
    const float* att_w1  = (const float*)d_in[25];
    const float* att_b1  = (const float*)d_in[26];
    const float* att_w2  = (const float*)d_in[27];
    const float* cluster = (const float*)d_in[28];
    const int*   adj_row = (const int*)d_in[29];
    const int*   adj_col = (const int*)d_in[30];
    const int E = in_sizes[1];

    float* out      = (float*)d_out;
    float* out_xbar = out;
    float* out_q    = out + (size_t)NNODES * NIN;
    float* out_pred = out_q + (size_t)NNODES * NZC;
    float* out_emb  = out_pred + (size_t)NNODES * NZC;

    float *h1, *h2, *h3, *z, *d1, *d2, *d3, *g, *t1, *t2, *t3, *t4;
    float *u, *zin, *zt, *ztopo, *scores, *embp, *mean, *rstd;
    __nv_bfloat16 *Ahi, *Alo, *Whi, *Wlo;
    cudaGetSymbolAddress((void**)&h1, g_h1);
    cudaGetSymbolAddress((void**)&h2, g_h2);
    cudaGetSymbolAddress((void**)&h3, g_h3);
    cudaGetSymbolAddress((void**)&z,  g_z);
    cudaGetSymbolAddress((void**)&d1, g_d1);
    cudaGetSymbolAddress((void**)&d2, g_d2);
    cudaGetSymbolAddress((void**)&d3, g_d3);
    cudaGetSymbolAddress((void**)&g,  g_g);
    cudaGetSymbolAddress((void**)&t1, g_t1);
    cudaGetSymbolAddress((void**)&t2, g_t2);
    cudaGetSymbolAddress((void**)&t3, g_t3);
    cudaGetSymbolAddress((void**)&t4, g_t4);
    cudaGetSymbolAddress((void**)&u,  g_u);
    cudaGetSymbolAddress((void**)&zin, g_zin);
    cudaGetSymbolAddress((void**)&zt, g_zt);
    cudaGetSymbolAddress((void**)&ztopo, g_ztopo);
    cudaGetSymbolAddress((void**)&scores, g_scores);
    cudaGetSymbolAddress((void**)&embp, g_embp);
    cudaGetSymbolAddress((void**)&mean, g_mean);
    cudaGetSymbolAddress((void**)&rstd, g_rstd);
    cudaGetSymbolAddress((void**)&Ahi, g_Ahi);
    cudaGetSymbolAddress((void**)&Alo, g_Alo);
    cudaGetSymbolAddress((void**)&Whi, g_Whi);
    cudaGetSymbolAddress((void**)&Wlo, g_Wlo);

    // ---------------- AE ----------------
    gemm_tc(x,  enc1_w, enc1_b, h1, NNODES, D1,   NIN,  2, Ahi, Alo, Whi, Wlo);
    gemm_tc(h1, enc2_w, enc2_b, h2, NNODES, D2,   D1,   2, Ahi, Alo, Whi, Wlo);
    gemm_tc(h2, enc3_w, enc3_b, h3, NNODES, D3,   D2,   2, Ahi, Alo, Whi, Wlo);
    gemm_tc(h3, zl_w,   zl_b,   z,  NNODES, NZC,  D3,   1, Ahi, Alo, Whi, Wlo);
    gemm_tc(z,  dec1_w, dec1_b, d1, NNODES, 2000, NZC,  2, Ahi, Alo, Whi, Wlo);
    gemm_tc(d1, dec2_w, dec2_b, d2, NNODES, 500,  2000, 2, Ahi, Alo, Whi, Wlo);
    gemm_tc(d2, dec3_w, dec3_b, d3, NNODES, 500,  500,  2, Ahi, Alo, Whi, Wlo);
    gemm_tc(d3, xbar_w, xbar_b, out_xbar, NNODES, NIN, 500, 1, Ahi, Alo, Whi, Wlo);

    // ---------------- topo GCN stack ----------------
    gemm_tc(x, t1_w, nullptr, g, NNODES, 500, NIN, 0, Ahi, Alo, Whi, Wlo);
    cudaMemsetAsync(t1, 0, (size_t)NNODES * 500 * sizeof(float), 0);
    spmm(g, adj_val, adj_row, adj_col, t1, 500, E);
    act(t1, (long)NNODES * 500, 0);
    batchnorm(t1, t1, NNODES, 500, mean, rstd);

    gemm_tc(t1, t2_w, nullptr, g, NNODES, 500, 500, 0, Ahi, Alo, Whi, Wlo);
    cudaMemsetAsync(t2, 0, (size_t)NNODES * 500 * sizeof(float), 0);
    spmm(g, adj_val, adj_row, adj_col, t2, 500, E);
    act(t2, (long)NNODES * 500, 0);
    batchnorm(t2, t2, NNODES, 500, mean, rstd);

    gemm_tc(t2, t3_w, nullptr, g, NNODES, 2000, 500, 0, Ahi, Alo, Whi, Wlo);
    cudaMemsetAsync(t3, 0, (size_t)NNODES * 2000 * sizeof(float), 0);
    spmm(g, adj_val, adj_row, adj_col, t3, 2000, E);
    act(t3, (long)NNODES * 2000, 0);
    batchnorm(t3, t3, NNODES, 2000, mean, rstd);

    gemm_tc(t3, t4_w, nullptr, g, NNODES, NZC, 2000, 0, Ahi, Alo, Whi, Wlo);
    cudaMemsetAsync(t4, 0, (size_t)NNODES * NZC * sizeof(float), 0);
    spmm(g, adj_val, adj_row, adj_col, t4, NZC, E);
    act(t4, (long)NNODES * NZC, 0);
    batchnorm(t4, t4, NNODES, NZC, mean, rstd);

    // ---------------- MLP gate u + z_in + agcn ----------------
    u_kernel<<<(NNODES * 32 + 255) / 256, 256>>>(t1, t2, t3, t4, mlpl_w, mlpl_b, u);
    {
        long total = (long)NNODES * COMS_D;
        zin_kernel<<<(int)((total + 255) / 256), 256>>>(t1, t2, t3, t4, u, zin);
    }
    gemm_tc(zin, agcn_w, nullptr, zt, NNODES, NZC, COMS_D, 0, Ahi, Alo, Whi, Wlo);
    cudaMemsetAsync(ztopo, 0, (size_t)NNODES * NZC * sizeof(float), 0);
    spmm(zt, adj_val, adj_row, adj_col, ztopo, NZC, E);
    act(ztopo, (long)NNODES * NZC, 1);
    batchnorm(ztopo, ztopo, NNODES, NZC, mean, rstd);

    // ---------------- attention fusion ----------------
    att_scores_kernel<<<(NNODES * 2 * 32 + 255) / 256, 256>>>(z, ztopo, att_w1, att_b1, att_w2, scores);
    {
        long total = (long)NNODES * NZC;
        att_combine_kernel<<<(int)((total + 255) / 256), 256>>>(z, ztopo, scores, embp);
    }
    batchnorm(embp, out_emb, NNODES, NZC, mean, rstd);
    rowsoftmax64_kernel<<<NNODES, 64>>>(out_emb, out_pred);

    // ---------------- Student-t q ----------------
    q_kernel<<<NNODES, 64>>>(z, cluster, out_q);
}

// round 7
// speedup vs baseline: 2.1219x; 1.1440x over previous
#include <cuda_runtime.h>
#include <cuda_bf16.h>
#include <math.h>
#include <stdint.h>

// ---------------------------------------------------------------------------
// Problem constants
// ---------------------------------------------------------------------------
#define NNODES 10000
#define NIN    2000
#define D1     500
#define D2     500
#define D3     2000
#define NZC    64
#define COMS_D 3064
#define EMAX   131072

// ---------------------------------------------------------------------------
// Scratch (device globals; no allocations allowed)
// ---------------------------------------------------------------------------
__device__ float g_zbuf [NNODES * NZC];
__device__ float g_gbuf [NNODES * 2000];      // gemm-before-spmm scratch
__device__ float g_traw [NNODES * 2000];      // spmm output (pre-BN)
__device__ float g_t1[NNODES * 500];
__device__ float g_t2[NNODES * 500];
__device__ float g_t3[NNODES * 2000];
__device__ float g_t4[NNODES * NZC];
__device__ float g_u [NNODES * 5];
__device__ float g_ztopo[NNODES * NZC];
__device__ float g_scores[NNODES * 2];
__device__ float g_embp[NNODES * NZC];
__device__ float g_mean[4096];
__device__ float g_rstd[4096];

// CSR build
__device__ int   g_cnt[NNODES + 1];
__device__ int   g_rowptr[NNODES + 1];
__device__ int   g_wp[NNODES];
__device__ int   g_scol[EMAX];
__device__ float g_sval[EMAX];

// bf16 split-precision ping-pong A buffers + weight buffers
__device__ __align__(256) __nv_bfloat16 g_A0hi[(size_t)NNODES * 3072];
__device__ __align__(256) __nv_bfloat16 g_A0lo[(size_t)NNODES * 3072];
__device__ __align__(256) __nv_bfloat16 g_A1hi[(size_t)NNODES * 3072];
__device__ __align__(256) __nv_bfloat16 g_A1lo[(size_t)NNODES * 3072];
__device__ __align__(256) __nv_bfloat16 g_Whi[2048 * 3072];
__device__ __align__(256) __nv_bfloat16 g_Wlo[2048 * 3072];

// ---------------------------------------------------------------------------
// PTX helpers (ldmatrix / mma.sync only)
// ---------------------------------------------------------------------------
__device__ __forceinline__ void ldsm4(uint32_t* r, uint32_t addr) {
    asm volatile("ldmatrix.sync.aligned.m8n8.x4.shared.b16 {%0,%1,%2,%3}, [%4];"
                 : "=r"(r[0]), "=r"(r[1]), "=r"(r[2]), "=r"(r[3]) : "r"(addr));
}
__device__ __forceinline__ uint32_t smem_u32(const void* p) {
    uint32_t a;
    asm("{ .reg .u64 t; cvta.to.shared.u64 t, %1; cvt.u32.u64 %0, t; }" : "=r"(a) : "l"(p));
    return a;
}
__device__ __forceinline__ void mma16816(float* c, const uint32_t* a, const uint32_t* b) {
    asm volatile(
        "mma.sync.aligned.m16n8k16.row.col.f32.bf16.bf16.f32 "
        "{%0,%1,%2,%3}, {%4,%5,%6,%7}, {%8,%9}, {%0,%1,%2,%3};"
        : "+f"(c[0]), "+f"(c[1]), "+f"(c[2]), "+f"(c[3])
        : "r"(a[0]), "r"(a[1]), "r"(a[2]), "r"(a[3]), "r"(b[0]), "r"(b[1]));
}
__device__ __forceinline__ void split_bf16(float v, __nv_bfloat16& h, __nv_bfloat16& l) {
    h = __float2bfloat16(v);
    l = __float2bfloat16(v - __bfloat162float(h));
}

// ---------------------------------------------------------------------------
// Split-bf16 mma.sync GEMM with optional fused hi/lo output for the next GEMM.
// BM=128 BN=64 BK=32, 256 threads, warps 4(m) x 2(n), warp tile 32x32.
// mode: 0 none, 1 +bias, 2 +bias+elu
// ---------------------------------------------------------------------------
#define ROWB 80
#define A_BYTES (128 * ROWB)
#define B_BYTES (64 * ROWB)

struct Prefetch { uint4 ahi[2], alo[2], bhi, blo; };

__device__ __forceinline__ void fetch_regs(
    Prefetch& p,
    const __nv_bfloat16* __restrict__ Ahi, const __nv_bfloat16* __restrict__ Alo,
    const __nv_bfloat16* __restrict__ Bhi, const __nv_bfloat16* __restrict__ Blo,
    int mBase, int M, int nBase, int N, int Kpad, int k0, int tid)
{
#pragma unroll
    for (int it = 0; it < 2; it++) {
        int t = tid + it * 256;
        int row = t >> 2, seg = t & 3;
        int gr = mBase + row;
        int sr = (gr < M) ? gr : 0;
        size_t off = (size_t)sr * Kpad + k0 + seg * 8;
        p.ahi[it] = *reinterpret_cast<const uint4*>(Ahi + off);
        p.alo[it] = *reinterpret_cast<const uint4*>(Alo + off);
    }
    {
        int row = tid >> 2, seg = tid & 3;
        int gn = nBase + row;
        int sn = (gn < N) ? gn : 0;
        size_t off = (size_t)sn * Kpad + k0 + seg * 8;
        p.bhi = *reinterpret_cast<const uint4*>(Bhi + off);
        p.blo = *reinterpret_cast<const uint4*>(Blo + off);
    }
}

__global__ __launch_bounds__(256) void mma_gemm_kernel(
    const __nv_bfloat16* __restrict__ Ahi, const __nv_bfloat16* __restrict__ Alo,
    const __nv_bfloat16* __restrict__ Bhi, const __nv_bfloat16* __restrict__ Blo,
    const float* __restrict__ bias, float* __restrict__ C,
    __nv_bfloat16* __restrict__ outHi, __nv_bfloat16* __restrict__ outLo, int KpadOut,
    int M, int Ncol, int Kpad, int mode)
{
    __shared__ __align__(256) char smem[2 * A_BYTES + 2 * B_BYTES];
    uint32_t sb = smem_u32(smem);
    int tid = threadIdx.x;
    int wid = tid >> 5, lane = tid & 31;
    int wm = wid & 3, wn = wid >> 2;
    int mBase = blockIdx.y * 128;
    int nBase = blockIdx.x * 64;

    uint32_t aHiS = sb;
    uint32_t aLoS = sb + A_BYTES;
    uint32_t bHiS = sb + 2 * A_BYTES;
    uint32_t bLoS = bHiS + B_BYTES;

    int arow0 = tid >> 2, aseg = tid & 3;
    uint32_t aOff0 = arow0 * ROWB + aseg * 16;
    uint32_t aOff1 = (arow0 + 64) * ROWB + aseg * 16;
    uint32_t bOff  = aOff0;

    float acc[2][4][4];
#pragma unroll
    for (int mt = 0; mt < 2; mt++)
#pragma unroll
        for (int nt = 0; nt < 4; nt++)
#pragma unroll
            for (int r = 0; r < 4; r++) acc[mt][nt][r] = 0.f;

    const int nc = Kpad >> 5;

    Prefetch pf;
    fetch_regs(pf, Ahi, Alo, Bhi, Blo, mBase, M, nBase, Ncol, Kpad, 0, tid);

    int lrow = (lane & 7) + ((lane >> 3) & 1) * 8;
    int lcol8 = (lane >> 4) * 8;

    for (int c = 0; c < nc; c++) {
        *reinterpret_cast<uint4*>(smem + aOff0)                        = pf.ahi[0];
        *reinterpret_cast<uint4*>(smem + aOff1)                        = pf.ahi[1];
        *reinterpret_cast<uint4*>(smem + A_BYTES + aOff0)              = pf.alo[0];
        *reinterpret_cast<uint4*>(smem + A_BYTES + aOff1)              = pf.alo[1];
        *reinterpret_cast<uint4*>(smem + 2 * A_BYTES + bOff)           = pf.bhi;
        *reinterpret_cast<uint4*>(smem + 2 * A_BYTES + B_BYTES + bOff) = pf.blo;
        __syncthreads();

        if (c + 1 < nc)
            fetch_regs(pf, Ahi, Alo, Bhi, Blo, mBase, M, nBase, Ncol, Kpad, (c + 1) * 32, tid);

#pragma unroll
        for (int ks = 0; ks < 2; ks++) {
            int kc = ks * 16 + lcol8;
            uint32_t ah[2][4], al[2][4];
#pragma unroll
            for (int mt = 0; mt < 2; mt++) {
                uint32_t o = (wm * 32 + mt * 16 + lrow) * ROWB + kc * 2;
                ldsm4(ah[mt], aHiS + o);
                ldsm4(al[mt], aLoS + o);
            }
            uint32_t bh[4][2], bl[4][2];
#pragma unroll
            for (int ntp = 0; ntp < 2; ntp++) {
                uint32_t o = (wn * 32 + ntp * 16 + lrow) * ROWB + kc * 2;
                uint32_t t[4];
                ldsm4(t, bHiS + o);
                bh[2 * ntp][0] = t[0]; bh[2 * ntp][1] = t[2];
                bh[2 * ntp + 1][0] = t[1]; bh[2 * ntp + 1][1] = t[3];
                ldsm4(t, bLoS + o);
                bl[2 * ntp][0] = t[0]; bl[2 * ntp][1] = t[2];
                bl[2 * ntp + 1][0] = t[1]; bl[2 * ntp + 1][1] = t[3];
            }
#pragma unroll
            for (int mt = 0; mt < 2; mt++)
#pragma unroll
                for (int nt = 0; nt < 4; nt++) {
                    mma16816(acc[mt][nt], ah[mt], bh[nt]);
                    mma16816(acc[mt][nt], ah[mt], bl[nt]);
                    mma16816(acc[mt][nt], al[mt], bh[nt]);
                }
        }
        __syncthreads();
    }

    // Epilogue: bias/elu, store fp32 C and (optionally) split-bf16 for next GEMM
    int qr = lane >> 2;
    int qc = (lane & 3) * 2;
#pragma unroll
    for (int mt = 0; mt < 2; mt++) {
#pragma unroll
        for (int nt = 0; nt < 4; nt++) {
#pragma unroll
            for (int half = 0; half < 2; half++) {
                int gr = mBase + wm * 32 + mt * 16 + qr + half * 8;
                if (gr >= M) continue;
#pragma unroll
                for (int e = 0; e < 2; e++) {
                    int gc = nBase + wn * 32 + nt * 8 + qc + e;
                    float v = acc[mt][nt][half * 2 + e];
                    if (gc < Ncol) {
                        if (mode >= 1) v += bias[gc];
                        if (mode == 2) v = v > 0.f ? v : expm1f(v);
                        C[(size_t)gr * Ncol + gc] = v;
                    } else {
                        v = 0.f;   // pad columns for the next GEMM's K
                    }
                    if (outHi && gc < KpadOut) {
                        __nv_bfloat16 h, l;
                        split_bf16(v, h, l);
                        outHi[(size_t)gr * KpadOut + gc] = h;
                        outLo[(size_t)gr * KpadOut + gc] = l;
                    }
                }
            }
        }
    }
}

// ---------------------------------------------------------------------------
// Conversions
// ---------------------------------------------------------------------------
__global__ void convA_kernel(const float* __restrict__ src,
                             __nv_bfloat16* __restrict__ hi, __nv_bfloat16* __restrict__ lo,
                             int K, int Kpad, long total)
{
    long i = (long)blockIdx.x * blockDim.x + threadIdx.x;
    if (i >= total) return;
    long r = i / Kpad;
    int  k = (int)(i - r * Kpad);
    float v = (k < K) ? src[r * K + k] : 0.f;
    __nv_bfloat16 h, l;
    split_bf16(v, h, l);
    hi[i] = h; lo[i] = l;
}

__global__ void convBT_kernel(const float* __restrict__ B,
                              __nv_bfloat16* __restrict__ bhi, __nv_bfloat16* __restrict__ blo,
                              int K, int N, int Kpad)
{
    __shared__ float sm[32][33];
    int k0 = blockIdx.x * 32, n0 = blockIdx.y * 32;
    int tx = threadIdx.x, ty = threadIdx.y;
    for (int i = ty; i < 32; i += 8) {
        int k = k0 + i, n = n0 + tx;
        sm[i][tx] = (k < K && n < N) ? B[(size_t)k * N + n] : 0.f;
    }
    __syncthreads();
    for (int i = ty; i < 32; i += 8) {
        int n = n0 + i, k = k0 + tx;
        if (n < N && k < Kpad) {
            __nv_bfloat16 h, l;
            split_bf16(sm[tx][i], h, l);
            bhi[(size_t)n * Kpad + k] = h;
            blo[(size_t)n * Kpad + k] = l;
        }
    }
}

// ---------------------------------------------------------------------------
// CSR build (once per launch) + CSR SpMM with fused activation
// ---------------------------------------------------------------------------
__global__ void csr_zero_kernel(int* cnt) {
    int i = blockIdx.x * blockDim.x + threadIdx.x;
    if (i <= NNODES) cnt[i] = 0;
}
__global__ void csr_count_kernel(const int* __restrict__ row, int* cnt, int E) {
    int e = blockIdx.x * blockDim.x + threadIdx.x;
    if (e < E) atomicAdd(&cnt[row[e] + 1], 1);
}
#define SCAN_PER 10   // 1024 * 10 >= NNODES
__global__ __launch_bounds__(1024) void csr_scan_kernel(const int* __restrict__ cnt,
                                                        int* rowptr, int* wp)
{
    __shared__ int sh[1024];
    int t = threadIdx.x;
    int base = t * SCAN_PER;
    int local[SCAN_PER];
    int s = 0;
#pragma unroll
    for (int i = 0; i < SCAN_PER; i++) {
        int idx = base + i;
        int v = (idx < NNODES) ? cnt[idx + 1] : 0;
        s += v;
        local[i] = s;
    }
    sh[t] = s;
    __syncthreads();
    for (int off = 1; off < 1024; off <<= 1) {
        int v = (t >= off) ? sh[t - off] : 0;
        __syncthreads();
        sh[t] += v;
        __syncthreads();
    }
    int prev = (t > 0) ? sh[t - 1] : 0;
    if (t == 0) rowptr[0] = 0;
#pragma unroll
    for (int i = 0; i < SCAN_PER; i++) {
        int idx = base + i;
        if (idx < NNODES) {
            rowptr[idx + 1] = prev + local[i];
            wp[idx] = (i == 0) ? prev : prev + local[i - 1];
        }
    }
}
__global__ void csr_scatter_kernel(const int* __restrict__ row, const int* __restrict__ col,
                                   const float* __restrict__ val, int* wp,
                                   int* scol, float* sval, int E)
{
    int e = blockIdx.x * blockDim.x + threadIdx.x;
    if (e >= E) return;
    int p = atomicAdd(&wp[row[e]], 1);
    scol[p] = col[e];
    sval[p] = val[e];
}

// act mode: 0 = elu(leaky_relu(x,0.2)), 1 = elu(x), 2 = none
__global__ void spmm_csr_kernel(const float* __restrict__ H,
                                const int* __restrict__ rowptr,
                                const int* __restrict__ scol, const float* __restrict__ sval,
                                float* __restrict__ out, int D, int actmode)
{
    int r = blockIdx.x;
    int s = rowptr[r], e_end = rowptr[r + 1];
    int nt = blockDim.x;
    float acc[8];
    int nreg = (D + nt - 1) / nt;
#pragma unroll 8
    for (int i = 0; i < 8; i++) acc[i] = 0.f;
    for (int e = s; e < e_end; e++) {
        int c = scol[e];
        float v = sval[e];
        const float* hrow = H + (size_t)c * D;
#pragma unroll 8
        for (int i = 0; i < 8; i++) {
            if (i >= nreg) break;
            int d = threadIdx.x + i * nt;
            if (d < D) acc[i] = fmaf(v, hrow[d], acc[i]);
        }
    }
#pragma unroll 8
    for (int i = 0; i < 8; i++) {
        if (i >= nreg) break;
        int d = threadIdx.x + i * nt;
        if (d < D) {
            float o = acc[i];
            if (actmode == 0) o = o > 0.f ? o : expm1f(0.2f * o);
            else if (actmode == 1) o = o > 0.f ? o : expm1f(o);
            out[(size_t)r * D + d] = o;
        }
    }
}
static inline void spmm_csr(const float* H, float* out, int D, int actmode,
                            const int* rowptr, const int* scol, const float* sval)
{
    int threads = (D >= 256) ? 256 : ((D + 31) & ~31);
    spmm_csr_kernel<<<NNODES, threads>>>(H, rowptr, scol, sval, out, D, actmode);
}

// ---------------------------------------------------------------------------
// BatchNorm (stats + apply with optional fused split-bf16 output)
// ---------------------------------------------------------------------------
__global__ void bn_stats_kernel(const float* __restrict__ h, int n, int d,
                                float* __restrict__ mean, float* __restrict__ rstd)
{
    __shared__ float ssum[8][32];
    __shared__ float ssq[8][32];
    int c = blockIdx.x * 32 + threadIdx.x;
    float s = 0.f, q = 0.f;
    if (c < d) {
        for (int r = threadIdx.y; r < n; r += 8) {
            float v = h[(size_t)r * d + c];
            s += v; q += v * v;
        }
    }
    ssum[threadIdx.y][threadIdx.x] = s;
    ssq[threadIdx.y][threadIdx.x] = q;
    __syncthreads();
    if (threadIdx.y == 0 && c < d) {
#pragma unroll
        for (int i = 1; i < 8; i++) { s += ssum[i][threadIdx.x]; q += ssq[i][threadIdx.x]; }
        float m = s / (float)n;
        float var = q / (float)n - m * m;
        if (var < 0.f) var = 0.f;
        mean[c] = m;
        rstd[c] = rsqrtf(var + 1e-5f);
    }
}
__global__ void bn_apply_kernel(const float* __restrict__ src, float* __restrict__ dst,
                                long total, int d, int Kpad,
                                const float* __restrict__ mean, const float* __restrict__ rstd,
                                __nv_bfloat16* __restrict__ outHi, __nv_bfloat16* __restrict__ outLo)
{
    long i = (long)blockIdx.x * blockDim.x + threadIdx.x;
    if (i >= total) return;
    long r = i / Kpad;
    int  c = (int)(i - r * Kpad);
    float v = 0.f;
    if (c < d) {
        v = (src[r * d + c] - mean[c]) * rstd[c];
        dst[r * d + c] = v;
    }
    if (outHi) {
        __nv_bfloat16 h, l;
        split_bf16(v, h, l);
        outHi[i] = h; outLo[i] = l;
    }
}
static inline void batchnorm(const float* src, float* dst, int n, int d,
                             float* mean, float* rstd,
                             __nv_bfloat16* outHi = nullptr, __nv_bfloat16* outLo = nullptr,
                             int Kpad = 0)
{
    dim3 bt(32, 8);
    bn_stats_kernel<<<(d + 31) / 32, bt>>>(src, n, d, mean, rstd);
    int kp = outHi ? Kpad : d;
    long total = (long)n * kp;
    bn_apply_kernel<<<(int)((total + 255) / 256), 256>>>(src, dst, total, d, kp, mean, rstd, outHi, outLo);
}

// ---------------------------------------------------------------------------
// Gate u, z_in (fused conversion), attention, softmax, q
// ---------------------------------------------------------------------------
__device__ __forceinline__ float coms_at(const float* t1, const float* t2,
                                         const float* t3, const float* t4,
                                         int n, int k)
{
    if (k < 500)  return t1[(size_t)n * 500 + k];
    if (k < 1000) return t2[(size_t)n * 500 + (k - 500)];
    if (k < 3000) return t3[(size_t)n * 2000 + (k - 1000)];
    return t4[(size_t)n * 64 + (k - 3000)];
}

__global__ void u_kernel(const float* __restrict__ t1, const float* __restrict__ t2,
                         const float* __restrict__ t3, const float* __restrict__ t4,
                         const float* __restrict__ W, const float* __restrict__ b,
                         float* __restrict__ u)
{
    int warp = (blockIdx.x * blockDim.x + threadIdx.x) >> 5;
    int lane = threadIdx.x & 31;
    if (warp >= NNODES) return;
    float acc[5] = {0.f, 0.f, 0.f, 0.f, 0.f};
    for (int k = lane; k < COMS_D; k += 32) {
        float v = coms_at(t1, t2, t3, t4, warp, k);
        const float* w = &W[(size_t)k * 5];
#pragma unroll
        for (int j = 0; j < 5; j++) acc[j] = fmaf(v, w[j], acc[j]);
    }
#pragma unroll
    for (int j = 0; j < 5; j++) {
        for (int off = 16; off > 0; off >>= 1)
            acc[j] += __shfl_down_sync(0xFFFFFFFF, acc[j], off);
    }
    if (lane == 0) {
        float l[5], m = -1e30f;
#pragma unroll
        for (int j = 0; j < 5; j++) { l[j] = tanhf(acc[j] + b[j]); m = fmaxf(m, l[j]); }
        float s = 0.f;
#pragma unroll
        for (int j = 0; j < 5; j++) { l[j] = expf(l[j] - m); s += l[j]; }
        float nrm = 0.f;
#pragma unroll
        for (int j = 0; j < 5; j++) { l[j] /= s; nrm += l[j] * l[j]; }
        nrm = fmaxf(sqrtf(nrm), 1e-12f);
#pragma unroll
        for (int j = 0; j < 5; j++) u[(size_t)warp * 5 + j] = l[j] / nrm;
    }
}

// z_in converted directly to split-bf16 [N, 3072] (cols 3064.. zero)
__global__ void zin_conv_kernel(const float* __restrict__ t1, const float* __restrict__ t2,
                                const float* __restrict__ t3, const float* __restrict__ t4,
                                const float* __restrict__ u,
                                __nv_bfloat16* __restrict__ hi, __nv_bfloat16* __restrict__ lo)
{
    long i = (long)blockIdx.x * blockDim.x + threadIdx.x;
    long total = (long)NNODES * 3072;
    if (i >= total) return;
    int n = (int)(i / 3072);
    int k = (int)(i % 3072);
    float v = 0.f;
    if (k < COMS_D) {
        int seg = (k < 500) ? 0 : (k < 1000) ? 1 : (k < 3000) ? 2 : 3;
        v = u[(size_t)n * 5 + seg] * coms_at(t1, t2, t3, t4, n, k);
    }
    __nv_bfloat16 h, l;
    split_bf16(v, h, l);
    hi[i] = h; lo[i] = l;
}

__global__ void att_scores_kernel(const float* __restrict__ z, const float* __restrict__ ztopo,
                                  const float* __restrict__ W1, const float* __restrict__ b1,
                                  const float* __restrict__ w2, float* __restrict__ scores)
{
    int gw = (blockIdx.x * blockDim.x + threadIdx.x) >> 5;
    int lane = threadIdx.x & 31;
    if (gw >= NNODES * 2) return;
    int n = gw >> 1;
    int br = gw & 1;
    const float* s = br ? &ztopo[(size_t)n * NZC] : &z[(size_t)n * NZC];
    float partial = 0.f;
    for (int j = lane; j < 128; j += 32) {
        float h = b1[j];
        for (int k = 0; k < NZC; k++) h = fmaf(s[k], W1[(size_t)k * 128 + j], h);
        partial = fmaf(tanhf(h), w2[j], partial);
    }
    for (int off = 16; off > 0; off >>= 1)
        partial += __shfl_down_sync(0xFFFFFFFF, partial, off);
    if (lane == 0) scores[(size_t)n * 2 + br] = partial;
}

__global__ void att_combine_kernel(const float* __restrict__ z, const float* __restrict__ ztopo,
                                   const float* __restrict__ scores, float* __restrict__ embp)
{
    long i = (long)blockIdx.x * blockDim.x + threadIdx.x;
    long total = (long)NNODES * NZC;
    if (i >= total) return;
    int n = (int)(i >> 6);
    float s0 = scores[(size_t)n * 2 + 0];
    float s1 = scores[(size_t)n * 2 + 1];
    float m = fmaxf(s0, s1);
    float e0 = expf(s0 - m), e1 = expf(s1 - m);
    float inv = 1.f / (e0 + e1);
    embp[i] = (e0 * inv) * z[i] + (e1 * inv) * ztopo[i];
}

__global__ void rowsoftmax64_kernel(const float* __restrict__ in, float* __restrict__ out)
{
    int n = blockIdx.x;
    int t = threadIdx.x;
    __shared__ float sh[64];
    float v = in[(size_t)n * 64 + t];
    sh[t] = v;
    __syncthreads();
    for (int s = 32; s > 0; s >>= 1) {
        if (t < s) sh[t] = fmaxf(sh[t], sh[t + s]);
        __syncthreads();
    }
    float m = sh[0];
    __syncthreads();
    float e = expf(v - m);
    sh[t] = e;
    __syncthreads();
    for (int s = 32; s > 0; s >>= 1) {
        if (t < s) sh[t] += sh[t + s];
        __syncthreads();
    }
    out[(size_t)n * 64 + t] = e / sh[0];
}

__global__ void q_kernel(const float* __restrict__ z, const float* __restrict__ cluster,
                         float* __restrict__ q)
{
    int n = blockIdx.x;
    int t = threadIdx.x;
    __shared__ float zs[64];
    __shared__ float red[64];
    zs[t] = z[(size_t)n * 64 + t];
    __syncthreads();
    float d2 = 0.f;
    const float* c = &cluster[(size_t)t * 64];
    for (int k = 0; k < 64; k++) {
        float diff = zs[k] - c[k];
        d2 = fmaf(diff, diff, d2);
    }
    float qv = 1.f / (1.f + d2);
    red[t] = qv;
    __syncthreads();
    for (int s = 32; s > 0; s >>= 1) {
        if (t < s) red[t] += red[t + s];
        __syncthreads();
    }
    q[(size_t)n * 64 + t] = qv / red[0];
}

// ---------------------------------------------------------------------------
// Host-side GEMM dispatch: A already converted (aHi/aLo, Kpad = (K+31)&~31);
// converts W, runs GEMM, optionally emits next-A split-bf16 (KpadOut).
// ---------------------------------------------------------------------------
static inline void gemm_pre(const __nv_bfloat16* aHi, const __nv_bfloat16* aLo,
                            const float* Bw, const float* bias, float* C,
                            __nv_bfloat16* outHi, __nv_bfloat16* outLo,
                            int M, int N, int K, int mode,
                            __nv_bfloat16* Whi, __nv_bfloat16* Wlo)
{
    int Kpad = (K + 31) & ~31;
    int KpadOut = (N + 31) & ~31;
    dim3 tg((Kpad + 31) / 32, (N + 31) / 32);
    convBT_kernel<<<tg, dim3(32, 8)>>>(Bw, Whi, Wlo, K, N, Kpad);
    dim3 grid((N + 63) / 64, (M + 127) / 128);
    mma_gemm_kernel<<<grid, 256>>>(aHi, aLo, Whi, Wlo, bias, C,
                                   outHi, outLo, KpadOut, M, N, Kpad, mode);
}

// ---------------------------------------------------------------------------
// Launch
// ---------------------------------------------------------------------------
extern "C" void kernel_launch(void* const* d_in, const int* in_sizes, int n_in,
                              void* d_out, int out_size)
{
    const float* x       = (const float*)d_in[0];
    const float* adj_val = (const float*)d_in[1];
    const float* enc1_w  = (const float*)d_in[2];
    const float* enc1_b  = (const float*)d_in[3];
    const float* enc2_w  = (const float*)d_in[4];
    const float* enc2_b  = (const float*)d_in[5];
    const float* enc3_w  = (const float*)d_in[6];
    const float* enc3_b  = (const float*)d_in[7];
    const float* zl_w    = (const float*)d_in[8];
    const float* zl_b    = (const float*)d_in[9];
    const float* dec1_w  = (const float*)d_in[10];
    const float* dec1_b  = (const float*)d_in[11];
    const float* dec2_w  = (const float*)d_in[12];
    const float* dec2_b  = (const float*)d_in[13];
    const float* dec3_w  = (const float*)d_in[14];
    const float* dec3_b  = (const float*)d_in[15];
    const float* xbar_w  = (const float*)d_in[16];
    const float* xbar_b  = (const float*)d_in[17];
    const float* t1_w    = (const float*)d_in[18];
    const float* t2_w    = (const float*)d_in[19];
    const float* t3_w    = (const float*)d_in[20];
    const float* t4_w    = (const float*)d_in[21];
    const float* agcn_w  = (const float*)d_in[22];
    const float* mlpl_w  = (const float*)d_in[23];
    const float* mlpl_b  = (const float*)d_in[24];
    const float* att_w1  = (const float*)d_in[25];
    const float* att_b1  = (const float*)d_in[26];
    const float* att_w2  = (const float*)d_in[27];
    const float* cluster = (const float*)d_in[28];
    const int*   adj_row = (const int*)d_in[29];
    const int*   adj_col = (const int*)d_in[30];
    const int E = in_sizes[1];

    float* out      = (float*)d_out;
    float* out_xbar = out;
    float* out_q    = out + (size_t)NNODES * NIN;
    float* out_pred = out_q + (size_t)NNODES * NZC;
    float* out_emb  = out_pred + (size_t)NNODES * NZC;

    float *z, *g, *traw, *t1, *t2, *t3, *t4, *u, *ztopo, *scores, *embp, *mean, *rstd;
    int *cnt, *rowptr, *wp, *scol;
    float *sval;
    __nv_bfloat16 *A0h, *A0l, *A1h, *A1l, *Wh, *Wl;
    cudaGetSymbolAddress((void**)&z,  g_zbuf);
    cudaGetSymbolAddress((void**)&g,  g_gbuf);
    cudaGetSymbolAddress((void**)&traw, g_traw);
    cudaGetSymbolAddress((void**)&t1, g_t1);
    cudaGetSymbolAddress((void**)&t2, g_t2);
    cudaGetSymbolAddress((void**)&t3, g_t3);
    cudaGetSymbolAddress((void**)&t4, g_t4);
    cudaGetSymbolAddress((void**)&u,  g_u);
    cudaGetSymbolAddress((void**)&ztopo, g_ztopo);
    cudaGetSymbolAddress((void**)&scores, g_scores);
    cudaGetSymbolAddress((void**)&embp, g_embp);
    cudaGetSymbolAddress((void**)&mean, g_mean);
    cudaGetSymbolAddress((void**)&rstd, g_rstd);
    cudaGetSymbolAddress((void**)&cnt, g_cnt);
    cudaGetSymbolAddress((void**)&rowptr, g_rowptr);
    cudaGetSymbolAddress((void**)&wp, g_wp);
    cudaGetSymbolAddress((void**)&scol, g_scol);
    cudaGetSymbolAddress((void**)&sval, g_sval);
    cudaGetSymbolAddress((void**)&A0h, g_A0hi);
    cudaGetSymbolAddress((void**)&A0l, g_A0lo);
    cudaGetSymbolAddress((void**)&A1h, g_A1hi);
    cudaGetSymbolAddress((void**)&A1l, g_A1lo);
    cudaGetSymbolAddress((void**)&Wh, g_Whi);
    cudaGetSymbolAddress((void**)&Wl, g_Wlo);

    // ---------------- CSR build (graph shared by all 5 SpMMs) ----------------
    csr_zero_kernel<<<(NNODES + 256) / 256, 256>>>(cnt);
    csr_count_kernel<<<(E + 255) / 256, 256>>>(adj_row, cnt, E);
    csr_scan_kernel<<<1, 1024>>>(cnt, rowptr, wp);
    csr_scatter_kernel<<<(E + 255) / 256, 256>>>(adj_row, adj_col, adj_val, wp, scol, sval, E);

    // ---------------- convert x once (feeds enc1 AND t1) ----------------
    {
        int Kpad = 2016;
        long tA = (long)NNODES * Kpad;
        convA_kernel<<<(int)((tA + 255) / 256), 256>>>(x, A0h, A0l, NIN, Kpad, tA);
    }

    // ---------------- topo t1 GEMM (uses x conversion) ----------------
    gemm_pre(A0h, A0l, t1_w, nullptr, g, nullptr, nullptr, NNODES, 500, NIN, 0, Wh, Wl);

    // ---------------- AE chain (ping-pong conversions fused in epilogue) ----
    gemm_pre(A0h, A0l, enc1_w, enc1_b, traw, A1h, A1l, NNODES, D1, NIN, 2, Wh, Wl);   // h1
    gemm_pre(A1h, A1l, enc2_w, enc2_b, traw, A0h, A0l, NNODES, D2, D1, 2, Wh, Wl);    // h2
    gemm_pre(A0h, A0l, enc3_w, enc3_b, traw, A1h, A1l, NNODES, D3, D2, 2, Wh, Wl);    // h3
    gemm_pre(A1h, A1l, zl_w, zl_b, z, A0h, A0l, NNODES, NZC, D3, 1, Wh, Wl);          // z
    gemm_pre(A0h, A0l, dec1_w, dec1_b, traw, A1h, A1l, NNODES, 2000, NZC, 2, Wh, Wl); // d1
    gemm_pre(A1h, A1l, dec2_w, dec2_b, traw, A0h, A0l, NNODES, 500, 2000, 2, Wh, Wl); // d2
    gemm_pre(A0h, A0l, dec3_w, dec3_b, traw, A1h, A1l, NNODES, 500, 500, 2, Wh, Wl);  // d3
    gemm_pre(A1h, A1l, xbar_w, xbar_b, out_xbar, nullptr, nullptr, NNODES, NIN, 500, 1, Wh, Wl);

    // ---------------- topo GCN stack (spmm+act fused; bn emits bf16) --------
    spmm_csr(g, traw, 500, 0, rowptr, scol, sval);
    batchnorm(traw, t1, NNODES, 500, mean, rstd, A0h, A0l, 512);
    gemm_pre(A0h, A0l, t2_w, nullptr, g, nullptr, nullptr, NNODES, 500, 500, 0, Wh, Wl);

    spmm_csr(g, traw, 500, 0, rowptr, scol, sval);
    batchnorm(traw, t2, NNODES, 500, mean, rstd, A0h, A0l, 512);
    gemm_pre(A0h, A0l, t3_w, nullptr, g, nullptr, nullptr, NNODES, 2000, 500, 0, Wh, Wl);

    spmm_csr(g, traw, 2000, 0, rowptr, scol, sval);
    batchnorm(traw, t3, NNODES, 2000, mean, rstd, A0h, A0l, 2016);
    gemm_pre(A0h, A0l, t4_w, nullptr, g, nullptr, nullptr, NNODES, NZC, 2000, 0, Wh, Wl);

    spmm_csr(g, traw, NZC, 0, rowptr, scol, sval);
    batchnorm(traw, t4, NNODES, NZC, mean, rstd);

    // ---------------- MLP gate u + z_in + agcn ----------------
    u_kernel<<<(NNODES * 32 + 255) / 256, 256>>>(t1, t2, t3, t4, mlpl_w, mlpl_b, u);
    {
        long total = (long)NNODES * 3072;
        zin_conv_kernel<<<(int)((total + 255) / 256), 256>>>(t1, t2, t3, t4, u, A0h, A0l);
    }
    gemm_pre(A0h, A0l, agcn_w, nullptr, g, nullptr, nullptr, NNODES, NZC, COMS_D, 0, Wh, Wl);
    spmm_csr(g, traw, NZC, 1, rowptr, scol, sval);   // elu only (active=False)
    batchnorm(traw, ztopo, NNODES, NZC, mean, rstd);

    // ---------------- attention fusion ----------------
    att_scores_kernel<<<(NNODES * 2 * 32 + 255) / 256, 256>>>(z, ztopo, att_w1, att_b1, att_w2, scores);
    {
        long total = (long)NNODES * NZC;
        att_combine_kernel<<<(int)((total + 255) / 256), 256>>>(z, ztopo, scores, embp);
    }
    batchnorm(embp, out_emb, NNODES, NZC, mean, rstd);
    rowsoftmax64_kernel<<<NNODES, 64>>>(out_emb, out_pred);

    // ---------------- Student-t q ----------------
    q_kernel<<<NNODES, 64>>>(z, cluster, out_q);
}

// round 8
// speedup vs baseline: 2.1253x; 1.0016x over previous
#include <cuda_runtime.h>
#include <cuda_bf16.h>
#include <math.h>
#include <stdint.h>

// ---------------------------------------------------------------------------
// Problem constants
// ---------------------------------------------------------------------------
#define NNODES 10000
#define NIN    2000
#define D1     500
#define D2     500
#define D3     2000
#define NZC    64
#define COMS_D 3064
#define EMAX   131072

// ---------------------------------------------------------------------------
// Scratch (device globals; no allocations allowed)
// ---------------------------------------------------------------------------
__device__ float g_zbuf [NNODES * NZC];
__device__ float g_gbuf [NNODES * 2000];      // gemm-before-spmm scratch
__device__ float g_traw [NNODES * 2000];      // spmm output (pre-BN)
__device__ float g_t1[NNODES * 500];
__device__ float g_t2[NNODES * 500];
__device__ float g_t3[NNODES * 2000];
__device__ float g_t4[NNODES * NZC];
__device__ float g_u [NNODES * 5];
__device__ float g_ztopo[NNODES * NZC];
__device__ float g_scores[NNODES * 2];
__device__ float g_embp[NNODES * NZC];
__device__ float g_mean[4096];
__device__ float g_rstd[4096];

// CSR build
__device__ int   g_cnt[NNODES + 1];
__device__ int   g_rowptr[NNODES + 1];
__device__ int   g_wp[NNODES];
__device__ int   g_scol[EMAX];
__device__ float g_sval[EMAX];

// bf16 split-precision ping-pong A buffers + weight buffers
__device__ __align__(256) __nv_bfloat16 g_A0hi[(size_t)NNODES * 3072];
__device__ __align__(256) __nv_bfloat16 g_A0lo[(size_t)NNODES * 3072];
__device__ __align__(256) __nv_bfloat16 g_A1hi[(size_t)NNODES * 3072];
__device__ __align__(256) __nv_bfloat16 g_A1lo[(size_t)NNODES * 3072];
__device__ __align__(256) __nv_bfloat16 g_Whi[2048 * 3072];
__device__ __align__(256) __nv_bfloat16 g_Wlo[2048 * 3072];

// ---------------------------------------------------------------------------
// PTX helpers (ldmatrix / mma.sync only)
// ---------------------------------------------------------------------------
__device__ __forceinline__ void ldsm4(uint32_t* r, uint32_t addr) {
    asm volatile("ldmatrix.sync.aligned.m8n8.x4.shared.b16 {%0,%1,%2,%3}, [%4];"
                 : "=r"(r[0]), "=r"(r[1]), "=r"(r[2]), "=r"(r[3]) : "r"(addr));
}
__device__ __forceinline__ uint32_t smem_u32(const void* p) {
    uint32_t a;
    asm("{ .reg .u64 t; cvta.to.shared.u64 t, %1; cvt.u32.u64 %0, t; }" : "=r"(a) : "l"(p));
    return a;
}
__device__ __forceinline__ void mma16816(float* c, const uint32_t* a, const uint32_t* b) {
    asm volatile(
        "mma.sync.aligned.m16n8k16.row.col.f32.bf16.bf16.f32 "
        "{%0,%1,%2,%3}, {%4,%5,%6,%7}, {%8,%9}, {%0,%1,%2,%3};"
        : "+f"(c[0]), "+f"(c[1]), "+f"(c[2]), "+f"(c[3])
        : "r"(a[0]), "r"(a[1]), "r"(a[2]), "r"(a[3]), "r"(b[0]), "r"(b[1]));
}
__device__ __forceinline__ void split_bf16(float v, __nv_bfloat16& h, __nv_bfloat16& l) {
    h = __float2bfloat16(v);
    l = __float2bfloat16(v - __bfloat162float(h));
}

// ---------------------------------------------------------------------------
// Split-bf16 mma.sync GEMM, double-buffered smem (ONE sync per K-chunk).
// BM=128 BN=64 BK=32, 256 threads, warps 4(m) x 2(n), warp tile 32x32.
// C may be nullptr (bf16 hi/lo output only). mode: 0 none, 1 +bias, 2 +bias+elu
// ---------------------------------------------------------------------------
#define ROWB 80
#define A_BYTES (128 * ROWB)
#define B_BYTES (64 * ROWB)
#define STAGE_BYTES (2 * A_BYTES + 2 * B_BYTES)   // 30720
#define GEMM_DSMEM (2 * STAGE_BYTES)              // 61440

struct Prefetch { uint4 ahi[2], alo[2], bhi, blo; };

__device__ __forceinline__ void fetch_regs(
    Prefetch& p,
    const __nv_bfloat16* __restrict__ Ahi, const __nv_bfloat16* __restrict__ Alo,
    const __nv_bfloat16* __restrict__ Bhi, const __nv_bfloat16* __restrict__ Blo,
    int mBase, int M, int nBase, int N, int Kpad, int k0, int tid)
{
#pragma unroll
    for (int it = 0; it < 2; it++) {
        int t = tid + it * 256;
        int row = t >> 2, seg = t & 3;
        int gr = mBase + row;
        int sr = (gr < M) ? gr : 0;
        size_t off = (size_t)sr * Kpad + k0 + seg * 8;
        p.ahi[it] = *reinterpret_cast<const uint4*>(Ahi + off);
        p.alo[it] = *reinterpret_cast<const uint4*>(Alo + off);
    }
    {
        int row = tid >> 2, seg = tid & 3;
        int gn = nBase + row;
        int sn = (gn < N) ? gn : 0;
        size_t off = (size_t)sn * Kpad + k0 + seg * 8;
        p.bhi = *reinterpret_cast<const uint4*>(Bhi + off);
        p.blo = *reinterpret_cast<const uint4*>(Blo + off);
    }
}

__global__ __launch_bounds__(256, 2) void mma_gemm_kernel(
    const __nv_bfloat16* __restrict__ Ahi, const __nv_bfloat16* __restrict__ Alo,
    const __nv_bfloat16* __restrict__ Bhi, const __nv_bfloat16* __restrict__ Blo,
    const float* __restrict__ bias, float* __restrict__ C,
    __nv_bfloat16* __restrict__ outHi, __nv_bfloat16* __restrict__ outLo, int KpadOut,
    int M, int Ncol, int Kpad, int mode)
{
    extern __shared__ __align__(256) char smem[];
    uint32_t sb = smem_u32(smem);
    int tid = threadIdx.x;
    int wid = tid >> 5, lane = tid & 31;
    int wm = wid & 3, wn = wid >> 2;
    int mBase = blockIdx.y * 128;
    int nBase = blockIdx.x * 64;

    int arow0 = tid >> 2, aseg = tid & 3;
    uint32_t aOff0 = arow0 * ROWB + aseg * 16;
    uint32_t aOff1 = (arow0 + 64) * ROWB + aseg * 16;
    uint32_t bOff  = aOff0;

    float acc[2][4][4];
#pragma unroll
    for (int mt = 0; mt < 2; mt++)
#pragma unroll
        for (int nt = 0; nt < 4; nt++)
#pragma unroll
            for (int r = 0; r < 4; r++) acc[mt][nt][r] = 0.f;

    const int nc = Kpad >> 5;

    Prefetch pf;
    fetch_regs(pf, Ahi, Alo, Bhi, Blo, mBase, M, nBase, Ncol, Kpad, 0, tid);

    int lrow = (lane & 7) + ((lane >> 3) & 1) * 8;
    int lcol8 = (lane >> 4) * 8;

    for (int c = 0; c < nc; c++) {
        char* buf = smem + (c & 1) * STAGE_BYTES;
        uint32_t bufU = sb + (c & 1) * STAGE_BYTES;

        *reinterpret_cast<uint4*>(buf + aOff0)                        = pf.ahi[0];
        *reinterpret_cast<uint4*>(buf + aOff1)                        = pf.ahi[1];
        *reinterpret_cast<uint4*>(buf + A_BYTES + aOff0)              = pf.alo[0];
        *reinterpret_cast<uint4*>(buf + A_BYTES + aOff1)              = pf.alo[1];
        *reinterpret_cast<uint4*>(buf + 2 * A_BYTES + bOff)           = pf.bhi;
        *reinterpret_cast<uint4*>(buf + 2 * A_BYTES + B_BYTES + bOff) = pf.blo;
        __syncthreads();

        if (c + 1 < nc)
            fetch_regs(pf, Ahi, Alo, Bhi, Blo, mBase, M, nBase, Ncol, Kpad, (c + 1) * 32, tid);

        uint32_t aHiS = bufU;
        uint32_t aLoS = bufU + A_BYTES;
        uint32_t bHiS = bufU + 2 * A_BYTES;
        uint32_t bLoS = bHiS + B_BYTES;

#pragma unroll
        for (int ks = 0; ks < 2; ks++) {
            int kc = ks * 16 + lcol8;
            uint32_t ah[2][4], al[2][4];
#pragma unroll
            for (int mt = 0; mt < 2; mt++) {
                uint32_t o = (wm * 32 + mt * 16 + lrow) * ROWB + kc * 2;
                ldsm4(ah[mt], aHiS + o);
                ldsm4(al[mt], aLoS + o);
            }
            uint32_t bh[4][2], bl[4][2];
#pragma unroll
            for (int ntp = 0; ntp < 2; ntp++) {
                uint32_t o = (wn * 32 + ntp * 16 + lrow) * ROWB + kc * 2;
                uint32_t t[4];
                ldsm4(t, bHiS + o);
                bh[2 * ntp][0] = t[0]; bh[2 * ntp][1] = t[2];
                bh[2 * ntp + 1][0] = t[1]; bh[2 * ntp + 1][1] = t[3];
                ldsm4(t, bLoS + o);
                bl[2 * ntp][0] = t[0]; bl[2 * ntp][1] = t[2];
                bl[2 * ntp + 1][0] = t[1]; bl[2 * ntp + 1][1] = t[3];
            }
#pragma unroll
            for (int mt = 0; mt < 2; mt++)
#pragma unroll
                for (int nt = 0; nt < 4; nt++) {
                    mma16816(acc[mt][nt], ah[mt], bh[nt]);
                    mma16816(acc[mt][nt], ah[mt], bl[nt]);
                    mma16816(acc[mt][nt], al[mt], bh[nt]);
                }
        }
        // no trailing sync: next iter stores to the other buffer; the
        // top-of-loop sync at iter c+1 proves all compute of iter c-1 done
        // before buffer (c+1)&1 is overwritten at iter c+1.  Epilogue uses
        // registers only.
    }

    // Epilogue: bias/elu, optional fp32 C, optional split-bf16 for next GEMM
    int qr = lane >> 2;
    int qc = (lane & 3) * 2;
#pragma unroll
    for (int mt = 0; mt < 2; mt++) {
#pragma unroll
        for (int nt = 0; nt < 4; nt++) {
#pragma unroll
            for (int half = 0; half < 2; half++) {
                int gr = mBase + wm * 32 + mt * 16 + qr + half * 8;
                if (gr >= M) continue;
#pragma unroll
                for (int e = 0; e < 2; e++) {
                    int gc = nBase + wn * 32 + nt * 8 + qc + e;
                    float v = acc[mt][nt][half * 2 + e];
                    if (gc < Ncol) {
                        if (mode >= 1) v += bias[gc];
                        if (mode == 2) v = v > 0.f ? v : expm1f(v);
                        if (C) C[(size_t)gr * Ncol + gc] = v;
                    } else {
                        v = 0.f;   // pad columns for the next GEMM's K
                    }
                    if (outHi && gc < KpadOut) {
                        __nv_bfloat16 h, l;
                        split_bf16(v, h, l);
                        outHi[(size_t)gr * KpadOut + gc] = h;
                        outLo[(size_t)gr * KpadOut + gc] = l;
                    }
                }
            }
        }
    }
}

// ---------------------------------------------------------------------------
// Conversions
// ---------------------------------------------------------------------------
__global__ void convA_kernel(const float* __restrict__ src,
                             __nv_bfloat16* __restrict__ hi, __nv_bfloat16* __restrict__ lo,
                             int K, int Kpad, long total)
{
    long i = (long)blockIdx.x * blockDim.x + threadIdx.x;
    if (i >= total) return;
    long r = i / Kpad;
    int  k = (int)(i - r * Kpad);
    float v = (k < K) ? src[r * K + k] : 0.f;
    __nv_bfloat16 h, l;
    split_bf16(v, h, l);
    hi[i] = h; lo[i] = l;
}

__global__ void convBT_kernel(const float* __restrict__ B,
                              __nv_bfloat16* __restrict__ bhi, __nv_bfloat16* __restrict__ blo,
                              int K, int N, int Kpad)
{
    __shared__ float sm[32][33];
    int k0 = blockIdx.x * 32, n0 = blockIdx.y * 32;
    int tx = threadIdx.x, ty = threadIdx.y;
    for (int i = ty; i < 32; i += 8) {
        int k = k0 + i, n = n0 + tx;
        sm[i][tx] = (k < K && n < N) ? B[(size_t)k * N + n] : 0.f;
    }
    __syncthreads();
    for (int i = ty; i < 32; i += 8) {
        int n = n0 + i, k = k0 + tx;
        if (n < N && k < Kpad) {
            __nv_bfloat16 h, l;
            split_bf16(sm[tx][i], h, l);
            bhi[(size_t)n * Kpad + k] = h;
            blo[(size_t)n * Kpad + k] = l;
        }
    }
}

// ---------------------------------------------------------------------------
// CSR build (once per launch) + CSR SpMM with fused activation
// ---------------------------------------------------------------------------
__global__ void csr_zero_kernel(int* cnt) {
    int i = blockIdx.x * blockDim.x + threadIdx.x;
    if (i <= NNODES) cnt[i] = 0;
}
__global__ void csr_count_kernel(const int* __restrict__ row, int* cnt, int E) {
    int e = blockIdx.x * blockDim.x + threadIdx.x;
    if (e < E) atomicAdd(&cnt[row[e] + 1], 1);
}
#define SCAN_PER 10   // 1024 * 10 >= NNODES
__global__ __launch_bounds__(1024) void csr_scan_kernel(const int* __restrict__ cnt,
                                                        int* rowptr, int* wp)
{
    __shared__ int sh[1024];
    int t = threadIdx.x;
    int base = t * SCAN_PER;
    int local[SCAN_PER];
    int s = 0;
#pragma unroll
    for (int i = 0; i < SCAN_PER; i++) {
        int idx = base + i;
        int v = (idx < NNODES) ? cnt[idx + 1] : 0;
        s += v;
        local[i] = s;
    }
    sh[t] = s;
    __syncthreads();
    for (int off = 1; off < 1024; off <<= 1) {
        int v = (t >= off) ? sh[t - off] : 0;
        __syncthreads();
        sh[t] += v;
        __syncthreads();
    }
    int prev = (t > 0) ? sh[t - 1] : 0;
    if (t == 0) rowptr[0] = 0;
#pragma unroll
    for (int i = 0; i < SCAN_PER; i++) {
        int idx = base + i;
        if (idx < NNODES) {
            rowptr[idx + 1] = prev + local[i];
            wp[idx] = (i == 0) ? prev : prev + local[i - 1];
        }
    }
}
__global__ void csr_scatter_kernel(const int* __restrict__ row, const int* __restrict__ col,
                                   const float* __restrict__ val, int* wp,
                                   int* scol, float* sval, int E)
{
    int e = blockIdx.x * blockDim.x + threadIdx.x;
    if (e >= E) return;
    int p = atomicAdd(&wp[row[e]], 1);
    scol[p] = col[e];
    sval[p] = val[e];
}

// act mode: 0 = elu(leaky_relu(x,0.2)), 1 = elu(x), 2 = none
__global__ void spmm_csr_kernel(const float* __restrict__ H,
                                const int* __restrict__ rowptr,
                                const int* __restrict__ scol, const float* __restrict__ sval,
                                float* __restrict__ out, int D, int actmode)
{
    int r = blockIdx.x;
    int s = rowptr[r], e_end = rowptr[r + 1];
    int nt = blockDim.x;
    float acc[8];
    int nreg = (D + nt - 1) / nt;
#pragma unroll 8
    for (int i = 0; i < 8; i++) acc[i] = 0.f;
    for (int e = s; e < e_end; e++) {
        int c = scol[e];
        float v = sval[e];
        const float* hrow = H + (size_t)c * D;
#pragma unroll 8
        for (int i = 0; i < 8; i++) {
            if (i >= nreg) break;
            int d = threadIdx.x + i * nt;
            if (d < D) acc[i] = fmaf(v, hrow[d], acc[i]);
        }
    }
#pragma unroll 8
    for (int i = 0; i < 8; i++) {
        if (i >= nreg) break;
        int d = threadIdx.x + i * nt;
        if (d < D) {
            float o = acc[i];
            if (actmode == 0) o = o > 0.f ? o : expm1f(0.2f * o);
            else if (actmode == 1) o = o > 0.f ? o : expm1f(o);
            out[(size_t)r * D + d] = o;
        }
    }
}
static inline void spmm_csr(const float* H, float* out, int D, int actmode,
                            const int* rowptr, const int* scol, const float* sval)
{
    int threads = (D >= 256) ? 256 : ((D + 31) & ~31);
    spmm_csr_kernel<<<NNODES, threads>>>(H, rowptr, scol, sval, out, D, actmode);
}

// ---------------------------------------------------------------------------
// BatchNorm (stats + apply with optional fused split-bf16 output)
// ---------------------------------------------------------------------------
__global__ void bn_stats_kernel(const float* __restrict__ h, int n, int d,
                                float* __restrict__ mean, float* __restrict__ rstd)
{
    __shared__ float ssum[8][32];
    __shared__ float ssq[8][32];
    int c = blockIdx.x * 32 + threadIdx.x;
    float s = 0.f, q = 0.f;
    if (c < d) {
        for (int r = threadIdx.y; r < n; r += 8) {
            float v = h[(size_t)r * d + c];
            s += v; q += v * v;
        }
    }
    ssum[threadIdx.y][threadIdx.x] = s;
    ssq[threadIdx.y][threadIdx.x] = q;
    __syncthreads();
    if (threadIdx.y == 0 && c < d) {
#pragma unroll
        for (int i = 1; i < 8; i++) { s += ssum[i][threadIdx.x]; q += ssq[i][threadIdx.x]; }
        float m = s / (float)n;
        float var = q / (float)n - m * m;
        if (var < 0.f) var = 0.f;
        mean[c] = m;
        rstd[c] = rsqrtf(var + 1e-5f);
    }
}
__global__ void bn_apply_kernel(const float* __restrict__ src, float* __restrict__ dst,
                                long total, int d, int Kpad,
                                const float* __restrict__ mean, const float* __restrict__ rstd,
                                __nv_bfloat16* __restrict__ outHi, __nv_bfloat16* __restrict__ outLo)
{
    long i = (long)blockIdx.x * blockDim.x + threadIdx.x;
    if (i >= total) return;
    long r = i / Kpad;
    int  c = (int)(i - r * Kpad);
    float v = 0.f;
    if (c < d) {
        v = (src[r * d + c] - mean[c]) * rstd[c];
        dst[r * d + c] = v;
    }
    if (outHi) {
        __nv_bfloat16 h, l;
        split_bf16(v, h, l);
        outHi[i] = h; outLo[i] = l;
    }
}
static inline void batchnorm(const float* src, float* dst, int n, int d,
                             float* mean, float* rstd,
                             __nv_bfloat16* outHi = nullptr, __nv_bfloat16* outLo = nullptr,
                             int Kpad = 0)
{
    dim3 bt(32, 8);
    bn_stats_kernel<<<(d + 31) / 32, bt>>>(src, n, d, mean, rstd);
    int kp = outHi ? Kpad : d;
    long total = (long)n * kp;
    bn_apply_kernel<<<(int)((total + 255) / 256), 256>>>(src, dst, total, d, kp, mean, rstd, outHi, outLo);
}

// ---------------------------------------------------------------------------
// Gate u, z_in (fused conversion), attention, softmax, q
// ---------------------------------------------------------------------------
__device__ __forceinline__ float coms_at(const float* t1, const float* t2,
                                         const float* t3, const float* t4,
                                         int n, int k)
{
    if (k < 500)  return t1[(size_t)n * 500 + k];
    if (k < 1000) return t2[(size_t)n * 500 + (k - 500)];
    if (k < 3000) return t3[(size_t)n * 2000 + (k - 1000)];
    return t4[(size_t)n * 64 + (k - 3000)];
}

__global__ void u_kernel(const float* __restrict__ t1, const float* __restrict__ t2,
                         const float* __restrict__ t3, const float* __restrict__ t4,
                         const float* __restrict__ W, const float* __restrict__ b,
                         float* __restrict__ u)
{
    int warp = (blockIdx.x * blockDim.x + threadIdx.x) >> 5;
    int lane = threadIdx.x & 31;
    if (warp >= NNODES) return;
    float acc[5] = {0.f, 0.f, 0.f, 0.f, 0.f};
    for (int k = lane; k < COMS_D; k += 32) {
        float v = coms_at(t1, t2, t3, t4, warp, k);
        const float* w = &W[(size_t)k * 5];
#pragma unroll
        for (int j = 0; j < 5; j++) acc[j] = fmaf(v, w[j], acc[j]);
    }
#pragma unroll
    for (int j = 0; j < 5; j++) {
        for (int off = 16; off > 0; off >>= 1)
            acc[j] += __shfl_down_sync(0xFFFFFFFF, acc[j], off);
    }
    if (lane == 0) {
        float l[5], m = -1e30f;
#pragma unroll
        for (int j = 0; j < 5; j++) { l[j] = tanhf(acc[j] + b[j]); m = fmaxf(m, l[j]); }
        float s = 0.f;
#pragma unroll
        for (int j = 0; j < 5; j++) { l[j] = expf(l[j] - m); s += l[j]; }
        float nrm = 0.f;
#pragma unroll
        for (int j = 0; j < 5; j++) { l[j] /= s; nrm += l[j] * l[j]; }
        nrm = fmaxf(sqrtf(nrm), 1e-12f);
#pragma unroll
        for (int j = 0; j < 5; j++) u[(size_t)warp * 5 + j] = l[j] / nrm;
    }
}

// z_in converted directly to split-bf16 [N, 3072] (cols 3064.. zero)
__global__ void zin_conv_kernel(const float* __restrict__ t1, const float* __restrict__ t2,
                                const float* __restrict__ t3, const float* __restrict__ t4,
                                const float* __restrict__ u,
                                __nv_bfloat16* __restrict__ hi, __nv_bfloat16* __restrict__ lo)
{
    long i = (long)blockIdx.x * blockDim.x + threadIdx.x;
    long total = (long)NNODES * 3072;
    if (i >= total) return;
    int n = (int)(i / 3072);
    int k = (int)(i % 3072);
    float v = 0.f;
    if (k < COMS_D) {
        int seg = (k < 500) ? 0 : (k < 1000) ? 1 : (k < 3000) ? 2 : 3;
        v = u[(size_t)n * 5 + seg] * coms_at(t1, t2, t3, t4, n, k);
    }
    __nv_bfloat16 h, l;
    split_bf16(v, h, l);
    hi[i] = h; lo[i] = l;
}

__global__ void att_scores_kernel(const float* __restrict__ z, const float* __restrict__ ztopo,
                                  const float* __restrict__ W1, const float* __restrict__ b1,
                                  const float* __restrict__ w2, float* __restrict__ scores)
{
    int gw = (blockIdx.x * blockDim.x + threadIdx.x) >> 5;
    int lane = threadIdx.x & 31;
    if (gw >= NNODES * 2) return;
    int n = gw >> 1;
    int br = gw & 1;
    const float* s = br ? &ztopo[(size_t)n * NZC] : &z[(size_t)n * NZC];
    float partial = 0.f;
    for (int j = lane; j < 128; j += 32) {
        float h = b1[j];
        for (int k = 0; k < NZC; k++) h = fmaf(s[k], W1[(size_t)k * 128 + j], h);
        partial = fmaf(tanhf(h), w2[j], partial);
    }
    for (int off = 16; off > 0; off >>= 1)
        partial += __shfl_down_sync(0xFFFFFFFF, partial, off);
    if (lane == 0) scores[(size_t)n * 2 + br] = partial;
}

__global__ void att_combine_kernel(const float* __restrict__ z, const float* __restrict__ ztopo,
                                   const float* __restrict__ scores, float* __restrict__ embp)
{
    long i = (long)blockIdx.x * blockDim.x + threadIdx.x;
    long total = (long)NNODES * NZC;
    if (i >= total) return;
    int n = (int)(i >> 6);
    float s0 = scores[(size_t)n * 2 + 0];
    float s1 = scores[(size_t)n * 2 + 1];
    float m = fmaxf(s0, s1);
    float e0 = expf(s0 - m), e1 = expf(s1 - m);
    float inv = 1.f / (e0 + e1);
    embp[i] = (e0 * inv) * z[i] + (e1 * inv) * ztopo[i];
}

__global__ void rowsoftmax64_kernel(const float* __restrict__ in, float* __restrict__ out)
{
    int n = blockIdx.x;
    int t = threadIdx.x;
    __shared__ float sh[64];
    float v = in[(size_t)n * 64 + t];
    sh[t] = v;
    __syncthreads();
    for (int s = 32; s > 0; s >>= 1) {
        if (t < s) sh[t] = fmaxf(sh[t], sh[t + s]);
        __syncthreads();
    }
    float m = sh[0];
    __syncthreads();
    float e = expf(v - m);
    sh[t] = e;
    __syncthreads();
    for (int s = 32; s > 0; s >>= 1) {
        if (t < s) sh[t] += sh[t + s];
        __syncthreads();
    }
    out[(size_t)n * 64 + t] = e / sh[0];
}

__global__ void q_kernel(const float* __restrict__ z, const float* __restrict__ cluster,
                         float* __restrict__ q)
{
    int n = blockIdx.x;
    int t = threadIdx.x;
    __shared__ float zs[64];
    __shared__ float red[64];
    zs[t] = z[(size_t)n * 64 + t];
    __syncthreads();
    float d2 = 0.f;
    const float* c = &cluster[(size_t)t * 64];
    for (int k = 0; k < 64; k++) {
        float diff = zs[k] - c[k];
        d2 = fmaf(diff, diff, d2);
    }
    float qv = 1.f / (1.f + d2);
    red[t] = qv;
    __syncthreads();
    for (int s = 32; s > 0; s >>= 1) {
        if (t < s) red[t] += red[t + s];
        __syncthreads();
    }
    q[(size_t)n * 64 + t] = qv / red[0];
}

// ---------------------------------------------------------------------------
// Host-side GEMM dispatch: A already converted (aHi/aLo, Kpad = (K+31)&~31);
// converts W, runs GEMM (double-buffered dynamic smem), optionally emits
// next-A split-bf16 (KpadOut). C may be nullptr.
// ---------------------------------------------------------------------------
static inline void gemm_pre(const __nv_bfloat16* aHi, const __nv_bfloat16* aLo,
                            const float* Bw, const float* bias, float* C,
                            __nv_bfloat16* outHi, __nv_bfloat16* outLo,
                            int M, int N, int K, int mode,
                            __nv_bfloat16* Whi, __nv_bfloat16* Wlo)
{
    int Kpad = (K + 31) & ~31;
    int KpadOut = (N + 31) & ~31;
    dim3 tg((Kpad + 31) / 32, (N + 31) / 32);
    convBT_kernel<<<tg, dim3(32, 8)>>>(Bw, Whi, Wlo, K, N, Kpad);
    cudaFuncSetAttribute(mma_gemm_kernel, cudaFuncAttributeMaxDynamicSharedMemorySize, GEMM_DSMEM);
    dim3 grid((N + 63) / 64, (M + 127) / 128);
    mma_gemm_kernel<<<grid, 256, GEMM_DSMEM>>>(aHi, aLo, Whi, Wlo, bias, C,
                                               outHi, outLo, KpadOut, M, N, Kpad, mode);
}

// ---------------------------------------------------------------------------
// Launch
// ---------------------------------------------------------------------------
extern "C" void kernel_launch(void* const* d_in, const int* in_sizes, int n_in,
                              void* d_out, int out_size)
{
    const float* x       = (const float*)d_in[0];
    const float* adj_val = (const float*)d_in[1];
    const float* enc1_w  = (const float*)d_in[2];
    const float* enc1_b  = (const float*)d_in[3];
    const float* enc2_w  = (const float*)d_in[4];
    const float* enc2_b  = (const float*)d_in[5];
    const float* enc3_w  = (const float*)d_in[6];
    const float* enc3_b  = (const float*)d_in[7];
    const float* zl_w    = (const float*)d_in[8];
    const float* zl_b    = (const float*)d_in[9];
    const float* dec1_w  = (const float*)d_in[10];
    const float* dec1_b  = (const float*)d_in[11];
    const float* dec2_w  = (const float*)d_in[12];
    const float* dec2_b  = (const float*)d_in[13];
    const float* dec3_w  = (const float*)d_in[14];
    const float* dec3_b  = (const float*)d_in[15];
    const float* xbar_w  = (const float*)d_in[16];
    const float* xbar_b  = (const float*)d_in[17];
    const float* t1_w    = (const float*)d_in[18];
    const float* t2_w    = (const float*)d_in[19];
    const float* t3_w    = (const float*)d_in[20];
    const float* t4_w    = (const float*)d_in[21];
    const float* agcn_w  = (const float*)d_in[22];
    const float* mlpl_w  = (const float*)d_in[23];
    const float* mlpl_b  = (const float*)d_in[24];
    const float* att_w1  = (const float*)d_in[25];
    const float* att_b1  = (const float*)d_in[26];
    const float* att_w2  = (const float*)d_in[27];
    const float* cluster = (const float*)d_in[28];
    const int*   adj_row = (const int*)d_in[29];
    const int*   adj_col = (const int*)d_in[30];
    const int E = in_sizes[1];

    float* out      = (float*)d_out;
    float* out_xbar = out;
    float* out_q    = out + (size_t)NNODES * NIN;
    float* out_pred = out_q + (size_t)NNODES * NZC;
    float* out_emb  = out_pred + (size_t)NNODES * NZC;

    float *z, *g, *traw, *t1, *t2, *t3, *t4, *u, *ztopo, *scores, *embp, *mean, *rstd;
    int *cnt, *rowptr, *wp, *scol;
    float *sval;
    __nv_bfloat16 *A0h, *A0l, *A1h, *A1l, *Wh, *Wl;
    cudaGetSymbolAddress((void**)&z,  g_zbuf);
    cudaGetSymbolAddress((void**)&g,  g_gbuf);
    cudaGetSymbolAddress((void**)&traw, g_traw);
    cudaGetSymbolAddress((void**)&t1, g_t1);
    cudaGetSymbolAddress((void**)&t2, g_t2);
    cudaGetSymbolAddress((void**)&t3, g_t3);
    cudaGetSymbolAddress((void**)&t4, g_t4);
    cudaGetSymbolAddress((void**)&u,  g_u);
    cudaGetSymbolAddress((void**)&ztopo, g_ztopo);
    cudaGetSymbolAddress((void**)&scores, g_scores);
    cudaGetSymbolAddress((void**)&embp, g_embp);
    cudaGetSymbolAddress((void**)&mean, g_mean);
    cudaGetSymbolAddress((void**)&rstd, g_rstd);
    cudaGetSymbolAddress((void**)&cnt, g_cnt);
    cudaGetSymbolAddress((void**)&rowptr, g_rowptr);
    cudaGetSymbolAddress((void**)&wp, g_wp);
    cudaGetSymbolAddress((void**)&scol, g_scol);
    cudaGetSymbolAddress((void**)&sval, g_sval);
    cudaGetSymbolAddress((void**)&A0h, g_A0hi);
    cudaGetSymbolAddress((void**)&A0l, g_A0lo);
    cudaGetSymbolAddress((void**)&A1h, g_A1hi);
    cudaGetSymbolAddress((void**)&A1l, g_A1lo);
    cudaGetSymbolAddress((void**)&Wh, g_Whi);
    cudaGetSymbolAddress((void**)&Wl, g_Wlo);

    // ---------------- CSR build (graph shared by all 5 SpMMs) ----------------
    csr_zero_kernel<<<(NNODES + 256) / 256, 256>>>(cnt);
    csr_count_kernel<<<(E + 255) / 256, 256>>>(adj_row, cnt, E);
    csr_scan_kernel<<<1, 1024>>>(cnt, rowptr, wp);
    csr_scatter_kernel<<<(E + 255) / 256, 256>>>(adj_row, adj_col, adj_val, wp, scol, sval, E);

    // ---------------- convert x once (feeds enc1 AND t1) ----------------
    {
        int Kpad = 2016;
        long tA = (long)NNODES * Kpad;
        convA_kernel<<<(int)((tA + 255) / 256), 256>>>(x, A0h, A0l, NIN, Kpad, tA);
    }

    // ---------------- topo t1 GEMM (uses x conversion) ----------------
    gemm_pre(A0h, A0l, t1_w, nullptr, g, nullptr, nullptr, NNODES, 500, NIN, 0, Wh, Wl);

    // ---------------- AE chain (ping-pong conversions fused in epilogue;
    //                  intermediate fp32 writes skipped) ----------------------
    gemm_pre(A0h, A0l, enc1_w, enc1_b, nullptr, A1h, A1l, NNODES, D1, NIN, 2, Wh, Wl);   // h1
    gemm_pre(A1h, A1l, enc2_w, enc2_b, nullptr, A0h, A0l, NNODES, D2, D1, 2, Wh, Wl);    // h2
    gemm_pre(A0h, A0l, enc3_w, enc3_b, nullptr, A1h, A1l, NNODES, D3, D2, 2, Wh, Wl);    // h3
    gemm_pre(A1h, A1l, zl_w, zl_b, z, A0h, A0l, NNODES, NZC, D3, 1, Wh, Wl);             // z
    gemm_pre(A0h, A0l, dec1_w, dec1_b, nullptr, A1h, A1l, NNODES, 2000, NZC, 2, Wh, Wl); // d1
    gemm_pre(A1h, A1l, dec2_w, dec2_b, nullptr, A0h, A0l, NNODES, 500, 2000, 2, Wh, Wl); // d2
    gemm_pre(A0h, A0l, dec3_w, dec3_b, nullptr, A1h, A1l, NNODES, 500, 500, 2, Wh, Wl);  // d3
    gemm_pre(A1h, A1l, xbar_w, xbar_b, out_xbar, nullptr, nullptr, NNODES, NIN, 500, 1, Wh, Wl);

    // ---------------- topo GCN stack (spmm+act fused; bn emits bf16) --------
    spmm_csr(g, traw, 500, 0, rowptr, scol, sval);
    batchnorm(traw, t1, NNODES, 500, mean, rstd, A0h, A0l, 512);
    gemm_pre(A0h, A0l, t2_w, nullptr, g, nullptr, nullptr, NNODES, 500, 500, 0, Wh, Wl);

    spmm_csr(g, traw, 500, 0, rowptr, scol, sval);
    batchnorm(traw, t2, NNODES, 500, mean, rstd, A0h, A0l, 512);
    gemm_pre(A0h, A0l, t3_w, nullptr, g, nullptr, nullptr, NNODES, 2000, 500, 0, Wh, Wl);

    spmm_csr(g, traw, 2000, 0, rowptr, scol, sval);
    batchnorm(traw, t3, NNODES, 2000, mean, rstd, A0h, A0l, 2016);
    gemm_pre(A0h, A0l, t4_w, nullptr, g, nullptr, nullptr, NNODES, NZC, 2000, 0, Wh, Wl);

    spmm_csr(g, traw, NZC, 0, rowptr, scol, sval);
    batchnorm(traw, t4, NNODES, NZC, mean, rstd);

    // ---------------- MLP gate u + z_in + agcn ----------------
    u_kernel<<<(NNODES * 32 + 255) / 256, 256>>>(t1, t2, t3, t4, mlpl_w, mlpl_b, u);
    {
        long total = (long)NNODES * 3072;
        zin_conv_kernel<<<(int)((total + 255) / 256), 256>>>(t1, t2, t3, t4, u, A0h, A0l);
    }
    gemm_pre(A0h, A0l, agcn_w, nullptr, g, nullptr, nullptr, NNODES, NZC, COMS_D, 0, Wh, Wl);
    spmm_csr(g, traw, NZC, 1, rowptr, scol, sval);   // elu only (active=False)
    batchnorm(traw, ztopo, NNODES, NZC, mean, rstd);

    // ---------------- attention fusion ----------------
    att_scores_kernel<<<(NNODES * 2 * 32 + 255) / 256, 256>>>(z, ztopo, att_w1, att_b1, att_w2, scores);
    {
        long total = (long)NNODES * NZC;
        att_combine_kernel<<<(int)((total + 255) / 256), 256>>>(z, ztopo, scores, embp);
    }
    batchnorm(embp, out_emb, NNODES, NZC, mean, rstd);
    rowsoftmax64_kernel<<<NNODES, 64>>>(out_emb, out_pred);

    // ---------------- Student-t q ----------------
    q_kernel<<<NNODES, 64>>>(z, cluster, out_q);
}